// round 5
// baseline (speedup 1.0000x reference)
#include <cuda_runtime.h>
#include <math.h>
#include <stdint.h>

// Problem constants
#define Bb   2
#define Tt   2048
#define Hh   1024
#define NHh  16
#define Dd   64
#define Mr   (Bb*Tt)          // 4096 rows
#define FFN  (4*Hh)           // 4096

// ---------------- scratch (static device memory; no allocations) ----------------
__device__ float g_z   [(size_t)Mr*Hh];
__device__ float g_q   [(size_t)Mr*Hh];
__device__ float g_k   [(size_t)Mr*Hh];
__device__ float g_v   [(size_t)Mr*Hh];
__device__ float g_u   [(size_t)Mr*Hh];
__device__ float g_pool[(size_t)Mr*Hh];
__device__ float g_o1  [(size_t)Mr*Hh];
__device__ float g_ffn [(size_t)Mr*FFN];
__device__ float g_trig[(size_t)Tt*32*2];

// ---------------- tf32 / async helpers ----------------
__device__ __forceinline__ unsigned f2tf(float f) {
    unsigned u;
    asm("cvt.rna.tf32.f32 %0, %1;" : "=r"(u) : "f"(f));
    return u;
}
__device__ __forceinline__ void mma8(float& c0, float& c1, float& c2, float& c3,
                                     unsigned a0, unsigned a1, unsigned a2, unsigned a3,
                                     unsigned b0, unsigned b1) {
    asm("mma.sync.aligned.m16n8k8.row.col.f32.tf32.tf32.f32 "
        "{%0,%1,%2,%3}, {%4,%5,%6,%7}, {%8,%9}, {%0,%1,%2,%3};"
        : "+f"(c0), "+f"(c1), "+f"(c2), "+f"(c3)
        : "r"(a0), "r"(a1), "r"(a2), "r"(a3), "r"(b0), "r"(b1));
}
__device__ __forceinline__ void cpa16(void* dst, const void* src) {
    unsigned d = (unsigned)__cvta_generic_to_shared(dst);
    asm volatile("cp.async.cg.shared.global [%0], [%1], 16;" :: "r"(d), "l"(src));
}
__device__ __forceinline__ void cpa_commit() { asm volatile("cp.async.commit_group;"); }
__device__ __forceinline__ void cpa_wait0()  { asm volatile("cp.async.wait_group 0;"); }

// ---------------- RMSNorm ----------------
__global__ __launch_bounds__(256) void rmsnorm_k(const float* __restrict__ x,
                                                 const float* __restrict__ w,
                                                 float* __restrict__ z) {
    int row = blockIdx.x;
    int t   = threadIdx.x;
    const float4* xr = (const float4*)(x + (size_t)row * Hh);
    float4 v = xr[t];
    float ss = v.x*v.x + v.y*v.y + v.z*v.z + v.w*v.w;
    #pragma unroll
    for (int o = 16; o; o >>= 1) ss += __shfl_xor_sync(0xffffffffu, ss, o);
    __shared__ float sred[8];
    if ((t & 31) == 0) sred[t >> 5] = ss;
    __syncthreads();
    if (t == 0) {
        float tot = 0.f;
        #pragma unroll
        for (int i = 0; i < 8; i++) tot += sred[i];
        sred[0] = rsqrtf(tot * (1.0f/Hh) + 1e-8f);
    }
    __syncthreads();
    float inv = sred[0];
    float4 wv = ((const float4*)w)[t];
    float4 o;
    o.x = v.x * wv.x * inv; o.y = v.y * wv.y * inv;
    o.z = v.z * wv.z * inv; o.w = v.w * wv.w * inv;
    ((float4*)(z + (size_t)row * Hh))[t] = o;
}

// ================= tf32 tensor-core GEMM, 2-stage cp.async pipeline =================
// C[M,N] = A[M,K] @ W[N,K]^T, block 128x128, K-slab 32, 256 threads (8 warps 2Mx4N)
// EPI: 0 store, 1 sr*xin+sg*acc, 2 gelu(acc+bias), 3 acc+bias+resid
#define PK 36            // smem k-stride (floats): conflict-free fragment loads
#define STG (128*PK)     // floats per stage per matrix
#define GEMM_SMEM (4*STG*4)   // bytes: 2 matrices x 2 stages

template<int EPI>
__device__ __forceinline__ void gemm_core(
    const float* __restrict__ A, const float* __restrict__ W, float* __restrict__ C,
    int M, int N, int K,
    const float* __restrict__ bias, const float* __restrict__ resid,
    const float* __restrict__ xin,  const float* __restrict__ gw,
    const float* __restrict__ rw)
{
    extern __shared__ float smf[];
    float* As = smf;            // [2][STG]
    float* Bs = smf + 2*STG;    // [2][STG]

    const int tid  = threadIdx.x;
    const int lane = tid & 31, warp = tid >> 5;
    const int grp  = lane >> 2, tig = lane & 3;
    const int wm = warp & 1, wn = warp >> 1;         // 2 x 4 warps
    const int m0 = blockIdx.y * 128, n0 = blockIdx.x * 128;

    const int lrow = tid >> 1;                        // 0..127
    const int lkb  = (tid & 1) * 16;                  // 0 or 16
    const float* Ap = A + (size_t)(m0 + lrow) * K + lkb;
    const float* Wp = W + (size_t)(n0 + lrow) * K + lkb;
    float* Asl = As + lrow*PK + lkb;
    float* Bsl = Bs + lrow*PK + lkb;

    float acc[4][4][4];
    #pragma unroll
    for (int a = 0; a < 4; a++)
        #pragma unroll
        for (int b = 0; b < 4; b++)
            #pragma unroll
            for (int c = 0; c < 4; c++) acc[a][b][c] = 0.f;

    const int nk = K >> 5;
    // prologue: slab 0 -> stage 0
    #pragma unroll
    for (int c = 0; c < 4; c++) {
        cpa16(Asl + c*4, Ap + c*4);
        cpa16(Bsl + c*4, Wp + c*4);
    }
    cpa_commit();

    for (int ks = 0; ks < nk; ks++) {
        cpa_wait0();
        __syncthreads();     // stage ks&1 ready; prev compute (stage ks&1 from 2 iters ago) done
        if (ks + 1 < nk) {
            const int k1 = (ks + 1) << 5, st = (ks + 1) & 1;
            #pragma unroll
            for (int c = 0; c < 4; c++) {
                cpa16(Asl + st*STG + c*4, Ap + k1 + c*4);
                cpa16(Bsl + st*STG + c*4, Wp + k1 + c*4);
            }
            cpa_commit();
        }
        const float* Ast = As + (ks & 1) * STG;
        const float* Bst = Bs + (ks & 1) * STG;

        #pragma unroll
        for (int kk = 0; kk < 4; kk++) {
            const int k = kk * 8;
            unsigned af[4][4], bf[4][2];
            #pragma unroll
            for (int tm = 0; tm < 4; tm++) {
                int rb = (wm*64 + tm*16 + grp) * PK + k;
                af[tm][0] = f2tf(Ast[rb + tig]);
                af[tm][1] = f2tf(Ast[rb + 8*PK + tig]);
                af[tm][2] = f2tf(Ast[rb + tig + 4]);
                af[tm][3] = f2tf(Ast[rb + 8*PK + tig + 4]);
            }
            #pragma unroll
            for (int tn = 0; tn < 4; tn++) {
                int nb = (wn*32 + tn*8 + grp) * PK + k;
                bf[tn][0] = f2tf(Bst[nb + tig]);
                bf[tn][1] = f2tf(Bst[nb + tig + 4]);
            }
            #pragma unroll
            for (int tm = 0; tm < 4; tm++)
                #pragma unroll
                for (int tn = 0; tn < 4; tn++)
                    mma8(acc[tm][tn][0], acc[tm][tn][1], acc[tm][tn][2], acc[tm][tn][3],
                         af[tm][0], af[tm][1], af[tm][2], af[tm][3],
                         bf[tn][0], bf[tn][1]);
        }
    }

    float sg = 0.f, sr = 0.f;
    if (EPI == 1) {
        sg = 1.f / (1.f + expf(-gw[0]));
        sr = 1.f / (1.f + expf(-rw[0]));
    }
    #pragma unroll
    for (int tm = 0; tm < 4; tm++) {
        #pragma unroll
        for (int tn = 0; tn < 4; tn++) {
            #pragma unroll
            for (int c = 0; c < 4; c++) {
                int row = m0 + wm*64 + tm*16 + grp + ((c >= 2) ? 8 : 0);
                int col = n0 + wn*32 + tn*8 + tig*2 + (c & 1);
                size_t idx = (size_t)row * N + col;
                float v = acc[tm][tn][c];
                if (EPI == 0) {
                    C[idx] = v;
                } else if (EPI == 1) {
                    C[idx] = sr * xin[idx] + sg * v;
                } else if (EPI == 2) {
                    v += bias[col];
                    C[idx] = 0.5f * v * (1.f + erff(v * 0.70710678118654752f));
                } else {
                    C[idx] = v + bias[col] + resid[idx];
                }
            }
        }
    }
}

template<int EPI>
__global__ __launch_bounds__(256) void gemm_tc(
    const float* __restrict__ A, const float* __restrict__ W, float* __restrict__ C,
    int M, int N, int K,
    const float* __restrict__ bias, const float* __restrict__ resid,
    const float* __restrict__ xin,  const float* __restrict__ gw,
    const float* __restrict__ rw)
{
    gemm_core<EPI>(A, W, C, M, N, K, bias, resid, xin, gw, rw);
}

__global__ __launch_bounds__(256) void proj4_tc(
    const float* __restrict__ A,
    const float* __restrict__ Wq, const float* __restrict__ Wk,
    const float* __restrict__ Wv, const float* __restrict__ Wu,
    float* __restrict__ Cq, float* __restrict__ Ck,
    float* __restrict__ Cv, float* __restrict__ Cu)
{
    const int which = blockIdx.z;
    const float* W = (which == 0) ? Wq : (which == 1) ? Wk : (which == 2) ? Wv : Wu;
    float* C       = (which == 0) ? Cq : (which == 1) ? Ck : (which == 2) ? Cv : Cu;
    gemm_core<0>(A, W, C, Mr, Hh, Hh, nullptr, nullptr, nullptr, nullptr, nullptr);
}

// ---------------- RoPE ----------------
__global__ void sincos_k(float* __restrict__ trig) {
    int idx = blockIdx.x * blockDim.x + threadIdx.x;
    if (idx >= Tt * 32) return;
    int t = idx >> 5, i = idx & 31;
    double invf = exp(-((double)(2 * i) / 64.0) * log(10000.0));
    double ang  = (double)t * invf;
    double s, c;
    sincos(ang, &s, &c);
    trig[idx*2+0] = (float)c;
    trig[idx*2+1] = (float)s;
}

// fused: applies rope to both Q and K in one launch
__global__ void rope2_k(float* __restrict__ Q, float* __restrict__ K,
                        const float* __restrict__ trig) {
    int idx = blockIdx.x * blockDim.x + threadIdx.x;   // 2*Mr*512 pairs
    float* X = (idx < Mr*512) ? Q : K;
    int id2 = idx & (Mr*512 - 1);
    int m = id2 >> 9;
    int p = id2 & 511;
    int h = p >> 5, i = p & 31;
    int t = m & (Tt - 1);
    size_t off = (size_t)m * Hh + h * 64 + 2 * i;
    float c = trig[(t*32 + i)*2 + 0];
    float s = trig[(t*32 + i)*2 + 1];
    float x0 = X[off], x1 = X[off+1];
    X[off]   = x0 * c - x1 * s;
    X[off+1] = x1 * c + x0 * s;
}

// ================= tf32 tensor-core attention (register-prefetched) =================
#define APK 68
__global__ __launch_bounds__(256) void attn_tc(
    const float* __restrict__ Qg, const float* __restrict__ Kg,
    const float* __restrict__ Vg, const float* __restrict__ rtab,
    float* __restrict__ Og)
{
    extern __shared__ unsigned smu[];
    unsigned* Qs = smu;                 // [i 64][d APK]
    unsigned* Ks = Qs + 64*APK;         // [j 64][d APK]
    unsigned* Vt = Ks + 64*APK;         // [d 64][j APK]
    unsigned* Ps = Vt + 64*APK;         // [i 64][j APK]
    float*    red  = (float*)(Ps + 64*APK);   // [64][4]
    float*    rabs = red + 64*4;              // [32]

    const int tid  = threadIdx.x;
    const int lane = tid & 31, warp = tid >> 5;
    const int grp  = lane >> 2, tig = lane & 3;
    const int wm = warp & 1, wn = warp >> 1;   // 2 x 4
    const int i0 = blockIdx.x * 64;
    const int bh = blockIdx.y;
    const int b = bh >> 4, h = bh & 15;
    const size_t base = ((size_t)b * Tt) * Hh + (size_t)h * 64;

    if (tid < 32) rabs[tid] = rtab[tid];

    {   // Q tile -> Qs[i][d], tf32
        const int r = tid >> 2, qc = (tid & 3) * 16;
        #pragma unroll
        for (int c = 0; c < 4; c++) {
            float4 qv = *(const float4*)(Qg + base + (size_t)(i0 + r) * Hh + qc + c*4);
            *(uint4*)&Qs[r*APK + qc + c*4] =
                make_uint4(f2tf(qv.x), f2tf(qv.y), f2tf(qv.z), f2tf(qv.w));
        }
    }

    float acc[2][2][4];
    #pragma unroll
    for (int a = 0; a < 2; a++)
        #pragma unroll
        for (int b2 = 0; b2 < 2; b2++)
            #pragma unroll
            for (int c = 0; c < 4; c++) acc[a][b2][c] = 0.f;
    float rsum[4] = {0.f, 0.f, 0.f, 0.f};
    const float scale = 0.125f;

    const int klr = tid >> 2, klc = (tid & 3) * 16;   // K loader
    const int vlj = tid & 63, vld = (tid >> 6) * 16;  // V loader (transpose)

    // prefetch tile 0 into registers
    float4 kv[4], vv[4];
    #pragma unroll
    for (int c = 0; c < 4; c++) {
        kv[c] = *(const float4*)(Kg + base + (size_t)klr * Hh + klc + c*4);
        vv[c] = *(const float4*)(Vg + base + (size_t)vlj * Hh + vld + c*4);
    }

    for (int jt = 0; jt < Tt/64; jt++) {
        const int j0 = jt * 64;
        __syncthreads();   // prev tile's PV done reading Ks/Vt/Ps
        #pragma unroll
        for (int c = 0; c < 4; c++) {
            *(uint4*)&Ks[klr*APK + klc + c*4] =
                make_uint4(f2tf(kv[c].x), f2tf(kv[c].y), f2tf(kv[c].z), f2tf(kv[c].w));
            Vt[(vld + c*4 + 0)*APK + vlj] = f2tf(vv[c].x);
            Vt[(vld + c*4 + 1)*APK + vlj] = f2tf(vv[c].y);
            Vt[(vld + c*4 + 2)*APK + vlj] = f2tf(vv[c].z);
            Vt[(vld + c*4 + 3)*APK + vlj] = f2tf(vv[c].w);
        }
        if (jt + 1 < Tt/64) {   // prefetch next tile; latency overlaps compute below
            const int jn = j0 + 64;
            #pragma unroll
            for (int c = 0; c < 4; c++) {
                kv[c] = *(const float4*)(Kg + base + (size_t)(jn + klr) * Hh + klc + c*4);
                vv[c] = *(const float4*)(Vg + base + (size_t)(jn + vlj) * Hh + vld + c*4);
            }
        }
        __syncthreads();

        // S = Q K^T
        float s[2][2][4];
        #pragma unroll
        for (int a = 0; a < 2; a++)
            #pragma unroll
            for (int b2 = 0; b2 < 2; b2++)
                #pragma unroll
                for (int c = 0; c < 4; c++) s[a][b2][c] = 0.f;
        #pragma unroll
        for (int kk = 0; kk < 8; kk++) {
            const int k = kk * 8;
            unsigned af[2][4], bf[2][2];
            #pragma unroll
            for (int tm = 0; tm < 2; tm++) {
                int rb = (wm*32 + tm*16 + grp) * APK + k;
                af[tm][0] = Qs[rb + tig];
                af[tm][1] = Qs[rb + 8*APK + tig];
                af[tm][2] = Qs[rb + tig + 4];
                af[tm][3] = Qs[rb + 8*APK + tig + 4];
            }
            #pragma unroll
            for (int tn = 0; tn < 2; tn++) {
                int nb = (wn*16 + tn*8 + grp) * APK + k;
                bf[tn][0] = Ks[nb + tig];
                bf[tn][1] = Ks[nb + tig + 4];
            }
            #pragma unroll
            for (int tm = 0; tm < 2; tm++)
                #pragma unroll
                for (int tn = 0; tn < 2; tn++)
                    mma8(s[tm][tn][0], s[tm][tn][1], s[tm][tn][2], s[tm][tn][3],
                         af[tm][0], af[tm][1], af[tm][2], af[tm][3],
                         bf[tn][0], bf[tn][1]);
        }

        // bias + clip + exp -> Ps, rsum
        #pragma unroll
        for (int tm = 0; tm < 2; tm++) {
            #pragma unroll
            for (int c = 0; c < 4; c++) {
                const int hi = (c >= 2) ? 1 : 0;
                const int il = wm*32 + tm*16 + grp + hi*8;
                const int i  = i0 + il;
                #pragma unroll
                for (int tn = 0; tn < 2; tn++) {
                    const int jl = wn*16 + tn*8 + tig*2 + (c & 1);
                    const int j  = j0 + jl;
                    int rel = j - i;
                    rel = (rel < -16) ? -16 : (rel > 15 ? 15 : rel);
                    float v = s[tm][tn][c] * scale + rabs[rel + 16];
                    v = fminf(fmaxf(v, -50.f), 50.f);
                    float e = expf(v);
                    rsum[tm*2 + hi] += e;
                    Ps[il*APK + jl] = f2tf(e);
                }
            }
        }
        __syncthreads();

        // O += P V
        #pragma unroll
        for (int kk = 0; kk < 8; kk++) {
            const int k = kk * 8;
            unsigned af[2][4], bf[2][2];
            #pragma unroll
            for (int tm = 0; tm < 2; tm++) {
                int rb = (wm*32 + tm*16 + grp) * APK + k;
                af[tm][0] = Ps[rb + tig];
                af[tm][1] = Ps[rb + 8*APK + tig];
                af[tm][2] = Ps[rb + tig + 4];
                af[tm][3] = Ps[rb + 8*APK + tig + 4];
            }
            #pragma unroll
            for (int tn = 0; tn < 2; tn++) {
                int nb = (wn*16 + tn*8 + grp) * APK + k;
                bf[tn][0] = Vt[nb + tig];
                bf[tn][1] = Vt[nb + tig + 4];
            }
            #pragma unroll
            for (int tm = 0; tm < 2; tm++)
                #pragma unroll
                for (int tn = 0; tn < 2; tn++)
                    mma8(acc[tm][tn][0], acc[tm][tn][1], acc[tm][tn][2], acc[tm][tn][3],
                         af[tm][0], af[tm][1], af[tm][2], af[tm][3],
                         bf[tn][0], bf[tn][1]);
        }
    }

    #pragma unroll
    for (int s2 = 0; s2 < 4; s2++) {
        float r = rsum[s2];
        r += __shfl_xor_sync(0xffffffffu, r, 1);
        r += __shfl_xor_sync(0xffffffffu, r, 2);
        if (tig == 0) {
            const int il = wm*32 + (s2 >> 1)*16 + grp + (s2 & 1)*8;
            red[il*4 + wn] = r;
        }
    }
    __syncthreads();

    #pragma unroll
    for (int tm = 0; tm < 2; tm++) {
        #pragma unroll
        for (int c = 0; c < 4; c++) {
            const int hi = (c >= 2) ? 1 : 0;
            const int il = wm*32 + tm*16 + grp + hi*8;
            float inv = 1.f / (red[il*4+0] + red[il*4+1] + red[il*4+2] + red[il*4+3]);
            #pragma unroll
            for (int tn = 0; tn < 2; tn++) {
                const int d = wn*16 + tn*8 + tig*2 + (c & 1);
                Og[base + (size_t)(i0 + il) * Hh + d] = acc[tm][tn][c] * inv;
            }
        }
    }
}

// ---------------- gated = sigmoid(U) * pooled ----------------
__global__ void gate_k(const float* __restrict__ U, const float* __restrict__ P,
                       float* __restrict__ G) {
    int i = blockIdx.x * blockDim.x + threadIdx.x;
    float4 u = ((const float4*)U)[i];
    float4 p = ((const float4*)P)[i];
    float4 o;
    o.x = p.x / (1.f + expf(-u.x));
    o.y = p.y / (1.f + expf(-u.y));
    o.z = p.z / (1.f + expf(-u.z));
    o.w = p.w / (1.f + expf(-u.w));
    ((float4*)G)[i] = o;
}

// ---------------- launch ----------------
#define ATTN_SMEM ((4*64*APK + 64*4 + 32) * 4)

extern "C" void kernel_launch(void* const* d_in, const int* in_sizes, int n_in,
                              void* d_out, int out_size) {
    const float* x    = (const float*)d_in[0];
    // d_in[1] attn_mask: all-True, no-op. d_in[2] pos_ids: unused by reference rope.
    const float* wq   = (const float*)d_in[3];
    const float* wk   = (const float*)d_in[4];
    const float* wv   = (const float*)d_in[5];
    const float* wu   = (const float*)d_in[6];
    const float* wo   = (const float*)d_in[7];
    const float* f1w  = (const float*)d_in[8];
    const float* f1b  = (const float*)d_in[9];
    const float* f2w  = (const float*)d_in[10];
    const float* f2b  = (const float*)d_in[11];
    const float* rmsw = (const float*)d_in[12];
    const float* rtab = (const float*)d_in[13];
    const float* gw   = (const float*)d_in[14];
    const float* rw   = (const float*)d_in[15];
    float* out = (float*)d_out;

    static float *z = nullptr, *q, *k, *v, *u, *pool, *o1, *ffn, *trig;
    if (!z) {
        cudaGetSymbolAddress((void**)&z,    g_z);
        cudaGetSymbolAddress((void**)&q,    g_q);
        cudaGetSymbolAddress((void**)&k,    g_k);
        cudaGetSymbolAddress((void**)&v,    g_v);
        cudaGetSymbolAddress((void**)&u,    g_u);
        cudaGetSymbolAddress((void**)&pool, g_pool);
        cudaGetSymbolAddress((void**)&o1,   g_o1);
        cudaGetSymbolAddress((void**)&ffn,  g_ffn);
        cudaGetSymbolAddress((void**)&trig, g_trig);
        cudaFuncSetAttribute(attn_tc,    cudaFuncAttributeMaxDynamicSharedMemorySize, ATTN_SMEM);
        cudaFuncSetAttribute(proj4_tc,   cudaFuncAttributeMaxDynamicSharedMemorySize, GEMM_SMEM);
        cudaFuncSetAttribute(gemm_tc<1>, cudaFuncAttributeMaxDynamicSharedMemorySize, GEMM_SMEM);
        cudaFuncSetAttribute(gemm_tc<2>, cudaFuncAttributeMaxDynamicSharedMemorySize, GEMM_SMEM);
        cudaFuncSetAttribute(gemm_tc<3>, cudaFuncAttributeMaxDynamicSharedMemorySize, GEMM_SMEM);
    }

    // 1. RMSNorm
    rmsnorm_k<<<Mr, 256>>>(x, rmsw, z);

    // 2. projections, all four in one launch
    proj4_tc<<<dim3(Hh/128, Mr/128, 4), 256, GEMM_SMEM>>>(z, wq, wk, wv, wu, q, k, v, u);

    // 3. RoPE on Q and K (one fused launch; attn becomes launch #5 for ncu)
    sincos_k<<<(Tt*32 + 255)/256, 256>>>(trig);
    rope2_k<<<(2*Mr*512)/256, 256>>>(q, k, trig);

    // 4. attention -> pooled   (launch #5: ncu capture target)
    attn_tc<<<dim3(Tt/64, Bb*NHh), 256, ATTN_SMEM>>>(q, k, v, rtab, pool);

    // 5. gated = sigmoid(U) * pooled
    gate_k<<<(Mr*Hh/4)/256, 256>>>(u, pool, z);

    // 6. wo GEMM + residual mix -> o1
    gemm_tc<1><<<dim3(Hh/128, Mr/128), 256, GEMM_SMEM>>>(z, wo, o1, Mr, Hh, Hh, nullptr, nullptr, x, gw, rw);

    // 7. FFN1 + bias + gelu -> ffn
    gemm_tc<2><<<dim3(FFN/128, Mr/128), 256, GEMM_SMEM>>>(o1, f1w, ffn, Mr, FFN, Hh, f1b, nullptr, nullptr, nullptr, nullptr);

    // 8. FFN2 + bias + residual -> out
    gemm_tc<3><<<dim3(Hh/128, Mr/128), 256, GEMM_SMEM>>>(ffn, f2w, out, Mr, Hh, FFN, f2b, o1, nullptr, nullptr, nullptr);
}

// round 7
// speedup vs baseline: 1.0735x; 1.0735x over previous
#include <cuda_runtime.h>
#include <math.h>
#include <stdint.h>

// Problem constants
#define Bb   2
#define Tt   2048
#define Hh   1024
#define NHh  16
#define Dd   64
#define Mr   (Bb*Tt)          // 4096 rows
#define FFN  (4*Hh)           // 4096
#define WSZ  (Hh*Hh)          // 1M floats

// ---------------- scratch (static device memory; no allocations) ----------------
__device__ float g_z   [(size_t)Mr*Hh];
__device__ float g_q   [(size_t)Mr*Hh];
__device__ float g_k   [(size_t)Mr*Hh];
__device__ float g_v   [(size_t)Mr*Hh];
__device__ float g_u   [(size_t)Mr*Hh];
__device__ float g_pool[(size_t)Mr*Hh];   // attn out; later reused as rounded-o1
__device__ float g_o1  [(size_t)Mr*Hh];
__device__ float g_ffn [(size_t)Mr*FFN];
__device__ float g_trig[(size_t)Tt*32*2];
__device__ float g_wr  [(size_t)13*WSZ];  // tf32-rounded weights: proj(4) | wo(1) | f1w(4) | f2w(4)

// ---------------- tf32 / async helpers ----------------
__device__ __forceinline__ unsigned f2tf(float f) {
    unsigned u;
    asm("cvt.rna.tf32.f32 %0, %1;" : "=r"(u) : "f"(f));
    return u;
}
__device__ __forceinline__ float f2tff(float f) { return __uint_as_float(f2tf(f)); }
__device__ __forceinline__ void mma8(float& c0, float& c1, float& c2, float& c3,
                                     unsigned a0, unsigned a1, unsigned a2, unsigned a3,
                                     unsigned b0, unsigned b1) {
    asm("mma.sync.aligned.m16n8k8.row.col.f32.tf32.tf32.f32 "
        "{%0,%1,%2,%3}, {%4,%5,%6,%7}, {%8,%9}, {%0,%1,%2,%3};"
        : "+f"(c0), "+f"(c1), "+f"(c2), "+f"(c3)
        : "r"(a0), "r"(a1), "r"(a2), "r"(a3), "r"(b0), "r"(b1));
}
__device__ __forceinline__ void cpa16(void* dst, const void* src) {
    unsigned d = (unsigned)__cvta_generic_to_shared(dst);
    asm volatile("cp.async.cg.shared.global [%0], [%1], 16;" :: "r"(d), "l"(src));
}
__device__ __forceinline__ void cpa_commit() { asm volatile("cp.async.commit_group;"); }
__device__ __forceinline__ void cpa_wait0()  { asm volatile("cp.async.wait_group 0;"); }

// ---------------- weight rounding (one cheap pass per launch) ----------------
__global__ void cvtw_k(const float* __restrict__ src, float* __restrict__ dst, int n4) {
    int i = blockIdx.x * blockDim.x + threadIdx.x;
    if (i >= n4) return;
    float4 v = ((const float4*)src)[i];
    float4 o;
    o.x = f2tff(v.x); o.y = f2tff(v.y); o.z = f2tff(v.z); o.w = f2tff(v.w);
    ((float4*)dst)[i] = o;
}

// ---------------- RMSNorm (outputs tf32-rounded z) ----------------
__global__ __launch_bounds__(256) void rmsnorm_k(const float* __restrict__ x,
                                                 const float* __restrict__ w,
                                                 float* __restrict__ z) {
    int row = blockIdx.x;
    int t   = threadIdx.x;
    const float4* xr = (const float4*)(x + (size_t)row * Hh);
    float4 v = xr[t];
    float ss = v.x*v.x + v.y*v.y + v.z*v.z + v.w*v.w;
    #pragma unroll
    for (int o = 16; o; o >>= 1) ss += __shfl_xor_sync(0xffffffffu, ss, o);
    __shared__ float sred[8];
    if ((t & 31) == 0) sred[t >> 5] = ss;
    __syncthreads();
    if (t == 0) {
        float tot = 0.f;
        #pragma unroll
        for (int i = 0; i < 8; i++) tot += sred[i];
        sred[0] = rsqrtf(tot * (1.0f/Hh) + 1e-8f);
    }
    __syncthreads();
    float inv = sred[0];
    float4 wv = ((const float4*)w)[t];
    float4 o;
    o.x = f2tff(v.x * wv.x * inv); o.y = f2tff(v.y * wv.y * inv);
    o.z = f2tff(v.z * wv.z * inv); o.w = f2tff(v.w * wv.w * inv);
    ((float4*)(z + (size_t)row * Hh))[t] = o;
}

// ================= tf32 GEMM, 2-stage cp.async, NO cvt in hot loop =================
// Inputs must be pre-rounded to tf32 bit patterns. Block 128x128, K-slab 32, 8 warps.
// EPI: 0 store, 1 dual-store (exact C + rounded C2) of sr*xin+sg*acc,
//      2 rounded gelu(acc+bias), 3 exact acc+bias+resid
#define PK 36
#define STG (128*PK)
#define GEMM_SMEM (4*STG*4)

template<int EPI>
__device__ __forceinline__ void gemm_core(
    const float* __restrict__ A, const float* __restrict__ W, float* __restrict__ C,
    int M, int N, int K,
    const float* __restrict__ bias, const float* __restrict__ resid,
    const float* __restrict__ xin,  const float* __restrict__ gw,
    const float* __restrict__ rw,   float* __restrict__ C2)
{
    extern __shared__ unsigned smu[];
    unsigned* As = smu;            // [2][STG]
    unsigned* Bs = smu + 2*STG;    // [2][STG]

    const int tid  = threadIdx.x;
    const int lane = tid & 31, warp = tid >> 5;
    const int grp  = lane >> 2, tig = lane & 3;
    const int wm = warp & 1, wn = warp >> 1;
    const int m0 = blockIdx.y * 128, n0 = blockIdx.x * 128;

    const int lrow = tid >> 1;
    const int lkb  = (tid & 1) * 16;
    const float* Ap = A + (size_t)(m0 + lrow) * K + lkb;
    const float* Wp = W + (size_t)(n0 + lrow) * K + lkb;
    unsigned* Asl = As + lrow*PK + lkb;
    unsigned* Bsl = Bs + lrow*PK + lkb;

    float acc[4][4][4];
    #pragma unroll
    for (int a = 0; a < 4; a++)
        #pragma unroll
        for (int b = 0; b < 4; b++)
            #pragma unroll
            for (int c = 0; c < 4; c++) acc[a][b][c] = 0.f;

    const int nk = K >> 5;
    #pragma unroll
    for (int c = 0; c < 4; c++) {
        cpa16(Asl + c*4, Ap + c*4);
        cpa16(Bsl + c*4, Wp + c*4);
    }
    cpa_commit();

    for (int ks = 0; ks < nk; ks++) {
        cpa_wait0();
        __syncthreads();
        if (ks + 1 < nk) {
            const int k1 = (ks + 1) << 5, st = (ks + 1) & 1;
            #pragma unroll
            for (int c = 0; c < 4; c++) {
                cpa16(Asl + st*STG + c*4, Ap + k1 + c*4);
                cpa16(Bsl + st*STG + c*4, Wp + k1 + c*4);
            }
            cpa_commit();
        }
        const unsigned* Ast = As + (ks & 1) * STG;
        const unsigned* Bst = Bs + (ks & 1) * STG;

        #pragma unroll
        for (int kk = 0; kk < 4; kk++) {
            const int k = kk * 8;
            unsigned af[4][4], bf[4][2];
            #pragma unroll
            for (int tm = 0; tm < 4; tm++) {
                int rb = (wm*64 + tm*16 + grp) * PK + k;
                af[tm][0] = Ast[rb + tig];
                af[tm][1] = Ast[rb + 8*PK + tig];
                af[tm][2] = Ast[rb + tig + 4];
                af[tm][3] = Ast[rb + 8*PK + tig + 4];
            }
            #pragma unroll
            for (int tn = 0; tn < 4; tn++) {
                int nb = (wn*32 + tn*8 + grp) * PK + k;
                bf[tn][0] = Bst[nb + tig];
                bf[tn][1] = Bst[nb + tig + 4];
            }
            #pragma unroll
            for (int tm = 0; tm < 4; tm++)
                #pragma unroll
                for (int tn = 0; tn < 4; tn++)
                    mma8(acc[tm][tn][0], acc[tm][tn][1], acc[tm][tn][2], acc[tm][tn][3],
                         af[tm][0], af[tm][1], af[tm][2], af[tm][3],
                         bf[tn][0], bf[tn][1]);
        }
    }

    float sg = 0.f, sr = 0.f;
    if (EPI == 1) {
        sg = 1.f / (1.f + expf(-gw[0]));
        sr = 1.f / (1.f + expf(-rw[0]));
    }
    #pragma unroll
    for (int tm = 0; tm < 4; tm++) {
        #pragma unroll
        for (int tn = 0; tn < 4; tn++) {
            #pragma unroll
            for (int c = 0; c < 4; c++) {
                int row = m0 + wm*64 + tm*16 + grp + ((c >= 2) ? 8 : 0);
                int col = n0 + wn*32 + tn*8 + tig*2 + (c & 1);
                size_t idx = (size_t)row * N + col;
                float v = acc[tm][tn][c];
                if (EPI == 0) {
                    C[idx] = v;
                } else if (EPI == 1) {
                    float o = sr * xin[idx] + sg * v;
                    C[idx]  = o;           // exact (residual path)
                    C2[idx] = f2tff(o);    // rounded (FFN1 input)
                } else if (EPI == 2) {
                    v += bias[col];
                    C[idx] = f2tff(0.5f * v * (1.f + erff(v * 0.70710678118654752f)));
                } else {
                    C[idx] = v + bias[col] + resid[idx];
                }
            }
        }
    }
}

template<int EPI>
__global__ __launch_bounds__(256) void gemm_tc(
    const float* __restrict__ A, const float* __restrict__ W, float* __restrict__ C,
    int M, int N, int K,
    const float* __restrict__ bias, const float* __restrict__ resid,
    const float* __restrict__ xin,  const float* __restrict__ gw,
    const float* __restrict__ rw,   float* __restrict__ C2)
{
    gemm_core<EPI>(A, W, C, M, N, K, bias, resid, xin, gw, rw, C2);
}

__global__ __launch_bounds__(256) void proj4_tc(
    const float* __restrict__ A, const float* __restrict__ Wr,
    float* __restrict__ Cq, float* __restrict__ Ck,
    float* __restrict__ Cv, float* __restrict__ Cu)
{
    const int which = blockIdx.z;
    const float* W = Wr + (size_t)which * WSZ;
    float* C = (which == 0) ? Cq : (which == 1) ? Ck : (which == 2) ? Cv : Cu;
    gemm_core<0>(A, W, C, Mr, Hh, Hh, nullptr, nullptr, nullptr, nullptr, nullptr, nullptr);
}

// ---------------- RoPE ----------------
__global__ void sincos_k(float* __restrict__ trig) {
    int idx = blockIdx.x * blockDim.x + threadIdx.x;
    if (idx >= Tt * 32) return;
    int t = idx >> 5, i = idx & 31;
    double invf = exp(-((double)(2 * i) / 64.0) * log(10000.0));
    double ang  = (double)t * invf;
    double s, c;
    sincos(ang, &s, &c);
    trig[idx*2+0] = (float)c;
    trig[idx*2+1] = (float)s;
}

__global__ void rope2_k(float* __restrict__ Q, float* __restrict__ K,
                        const float* __restrict__ trig) {
    int idx = blockIdx.x * blockDim.x + threadIdx.x;
    float* X = (idx < Mr*512) ? Q : K;
    int id2 = idx & (Mr*512 - 1);
    int m = id2 >> 9;
    int p = id2 & 511;
    int h = p >> 5, i = p & 31;
    int t = m & (Tt - 1);
    size_t off = (size_t)m * Hh + h * 64 + 2 * i;
    float c = trig[(t*32 + i)*2 + 0];
    float s = trig[(t*32 + i)*2 + 1];
    float x0 = X[off], x1 = X[off+1];
    X[off]   = x0 * c - x1 * s;
    X[off+1] = x1 * c + x0 * s;
}

// ================= tf32 tensor-core attention (Round-4 version) =================
#define APK 68
__global__ __launch_bounds__(256) void attn_tc(
    const float* __restrict__ Qg, const float* __restrict__ Kg,
    const float* __restrict__ Vg, const float* __restrict__ rtab,
    float* __restrict__ Og)
{
    extern __shared__ unsigned smu[];
    unsigned* Qs = smu;
    unsigned* Ks = Qs + 64*APK;
    unsigned* Vt = Ks + 64*APK;
    unsigned* Ps = Vt + 64*APK;
    float*    red  = (float*)(Ps + 64*APK);
    float*    rabs = red + 64*4;

    const int tid  = threadIdx.x;
    const int lane = tid & 31, warp = tid >> 5;
    const int grp  = lane >> 2, tig = lane & 3;
    const int wm = warp & 1, wn = warp >> 1;
    const int i0 = blockIdx.x * 64;
    const int bh = blockIdx.y;
    const int b = bh >> 4, h = bh & 15;
    const size_t base = ((size_t)b * Tt) * Hh + (size_t)h * 64;

    if (tid < 32) rabs[tid] = rtab[tid];

    {
        const int r = tid >> 2, qc = (tid & 3) * 16;
        #pragma unroll
        for (int c = 0; c < 4; c++) {
            float4 qv = *(const float4*)(Qg + base + (size_t)(i0 + r) * Hh + qc + c*4);
            *(uint4*)&Qs[r*APK + qc + c*4] =
                make_uint4(f2tf(qv.x), f2tf(qv.y), f2tf(qv.z), f2tf(qv.w));
        }
    }

    float acc[2][2][4];
    #pragma unroll
    for (int a = 0; a < 2; a++)
        #pragma unroll
        for (int b2 = 0; b2 < 2; b2++)
            #pragma unroll
            for (int c = 0; c < 4; c++) acc[a][b2][c] = 0.f;
    float rsum[4] = {0.f, 0.f, 0.f, 0.f};
    const float scale = 0.125f;

    const int klr = tid >> 2, klc = (tid & 3) * 16;
    const int vlj = tid & 63, vld = (tid >> 6) * 16;

    for (int jt = 0; jt < Tt/64; jt++) {
        const int j0 = jt * 64;
        float4 kv[4], vv[4];
        #pragma unroll
        for (int c = 0; c < 4; c++) {
            kv[c] = *(const float4*)(Kg + base + (size_t)(j0 + klr) * Hh + klc + c*4);
            vv[c] = *(const float4*)(Vg + base + (size_t)(j0 + vlj) * Hh + vld + c*4);
        }
        __syncthreads();
        #pragma unroll
        for (int c = 0; c < 4; c++) {
            *(uint4*)&Ks[klr*APK + klc + c*4] =
                make_uint4(f2tf(kv[c].x), f2tf(kv[c].y), f2tf(kv[c].z), f2tf(kv[c].w));
            Vt[(vld + c*4 + 0)*APK + vlj] = f2tf(vv[c].x);
            Vt[(vld + c*4 + 1)*APK + vlj] = f2tf(vv[c].y);
            Vt[(vld + c*4 + 2)*APK + vlj] = f2tf(vv[c].z);
            Vt[(vld + c*4 + 3)*APK + vlj] = f2tf(vv[c].w);
        }
        __syncthreads();

        float s[2][2][4];
        #pragma unroll
        for (int a = 0; a < 2; a++)
            #pragma unroll
            for (int b2 = 0; b2 < 2; b2++)
                #pragma unroll
                for (int c = 0; c < 4; c++) s[a][b2][c] = 0.f;
        #pragma unroll
        for (int kk = 0; kk < 8; kk++) {
            const int k = kk * 8;
            unsigned af[2][4], bf[2][2];
            #pragma unroll
            for (int tm = 0; tm < 2; tm++) {
                int rb = (wm*32 + tm*16 + grp) * APK + k;
                af[tm][0] = Qs[rb + tig];
                af[tm][1] = Qs[rb + 8*APK + tig];
                af[tm][2] = Qs[rb + tig + 4];
                af[tm][3] = Qs[rb + 8*APK + tig + 4];
            }
            #pragma unroll
            for (int tn = 0; tn < 2; tn++) {
                int nb = (wn*16 + tn*8 + grp) * APK + k;
                bf[tn][0] = Ks[nb + tig];
                bf[tn][1] = Ks[nb + tig + 4];
            }
            #pragma unroll
            for (int tm = 0; tm < 2; tm++)
                #pragma unroll
                for (int tn = 0; tn < 2; tn++)
                    mma8(s[tm][tn][0], s[tm][tn][1], s[tm][tn][2], s[tm][tn][3],
                         af[tm][0], af[tm][1], af[tm][2], af[tm][3],
                         bf[tn][0], bf[tn][1]);
        }

        #pragma unroll
        for (int tm = 0; tm < 2; tm++) {
            #pragma unroll
            for (int c = 0; c < 4; c++) {
                const int hi = (c >= 2) ? 1 : 0;
                const int il = wm*32 + tm*16 + grp + hi*8;
                const int i  = i0 + il;
                #pragma unroll
                for (int tn = 0; tn < 2; tn++) {
                    const int jl = wn*16 + tn*8 + tig*2 + (c & 1);
                    const int j  = j0 + jl;
                    int rel = j - i;
                    rel = (rel < -16) ? -16 : (rel > 15 ? 15 : rel);
                    float v = s[tm][tn][c] * scale + rabs[rel + 16];
                    v = fminf(fmaxf(v, -50.f), 50.f);
                    float e = expf(v);
                    rsum[tm*2 + hi] += e;
                    Ps[il*APK + jl] = f2tf(e);
                }
            }
        }
        __syncthreads();

        #pragma unroll
        for (int kk = 0; kk < 8; kk++) {
            const int k = kk * 8;
            unsigned af[2][4], bf[2][2];
            #pragma unroll
            for (int tm = 0; tm < 2; tm++) {
                int rb = (wm*32 + tm*16 + grp) * APK + k;
                af[tm][0] = Ps[rb + tig];
                af[tm][1] = Ps[rb + 8*APK + tig];
                af[tm][2] = Ps[rb + tig + 4];
                af[tm][3] = Ps[rb + 8*APK + tig + 4];
            }
            #pragma unroll
            for (int tn = 0; tn < 2; tn++) {
                int nb = (wn*16 + tn*8 + grp) * APK + k;
                bf[tn][0] = Vt[nb + tig];
                bf[tn][1] = Vt[nb + tig + 4];
            }
            #pragma unroll
            for (int tm = 0; tm < 2; tm++)
                #pragma unroll
                for (int tn = 0; tn < 2; tn++)
                    mma8(acc[tm][tn][0], acc[tm][tn][1], acc[tm][tn][2], acc[tm][tn][3],
                         af[tm][0], af[tm][1], af[tm][2], af[tm][3],
                         bf[tn][0], bf[tn][1]);
        }
    }

    #pragma unroll
    for (int s2 = 0; s2 < 4; s2++) {
        float r = rsum[s2];
        r += __shfl_xor_sync(0xffffffffu, r, 1);
        r += __shfl_xor_sync(0xffffffffu, r, 2);
        if (tig == 0) {
            const int il = wm*32 + (s2 >> 1)*16 + grp + (s2 & 1)*8;
            red[il*4 + wn] = r;
        }
    }
    __syncthreads();

    #pragma unroll
    for (int tm = 0; tm < 2; tm++) {
        #pragma unroll
        for (int c = 0; c < 4; c++) {
            const int hi = (c >= 2) ? 1 : 0;
            const int il = wm*32 + tm*16 + grp + hi*8;
            float inv = 1.f / (red[il*4+0] + red[il*4+1] + red[il*4+2] + red[il*4+3]);
            #pragma unroll
            for (int tn = 0; tn < 2; tn++) {
                const int d = wn*16 + tn*8 + tig*2 + (c & 1);
                Og[base + (size_t)(i0 + il) * Hh + d] = acc[tm][tn][c] * inv;
            }
        }
    }
}

// ---------------- gated = sigmoid(U) * pooled (rounded output) ----------------
__global__ void gate_k(const float* __restrict__ U, const float* __restrict__ P,
                       float* __restrict__ G) {
    int i = blockIdx.x * blockDim.x + threadIdx.x;
    float4 u = ((const float4*)U)[i];
    float4 p = ((const float4*)P)[i];
    float4 o;
    o.x = f2tff(p.x / (1.f + expf(-u.x)));
    o.y = f2tff(p.y / (1.f + expf(-u.y)));
    o.z = f2tff(p.z / (1.f + expf(-u.z)));
    o.w = f2tff(p.w / (1.f + expf(-u.w)));
    ((float4*)G)[i] = o;
}

// ---------------- launch ----------------
#define ATTN_SMEM ((4*64*APK + 64*4 + 32) * 4)

extern "C" void kernel_launch(void* const* d_in, const int* in_sizes, int n_in,
                              void* d_out, int out_size) {
    const float* x    = (const float*)d_in[0];
    // d_in[1] attn_mask: all-True, no-op. d_in[2] pos_ids: unused by reference rope.
    const float* wq   = (const float*)d_in[3];
    const float* wk   = (const float*)d_in[4];
    const float* wv   = (const float*)d_in[5];
    const float* wu   = (const float*)d_in[6];
    const float* wo   = (const float*)d_in[7];
    const float* f1w  = (const float*)d_in[8];
    const float* f1b  = (const float*)d_in[9];
    const float* f2w  = (const float*)d_in[10];
    const float* f2b  = (const float*)d_in[11];
    const float* rmsw = (const float*)d_in[12];
    const float* rtab = (const float*)d_in[13];
    const float* gw   = (const float*)d_in[14];
    const float* rw   = (const float*)d_in[15];
    float* out = (float*)d_out;

    static float *z = nullptr, *q, *k, *v, *u, *pool, *o1, *ffn, *trig, *wr;
    if (!z) {
        cudaGetSymbolAddress((void**)&z,    g_z);
        cudaGetSymbolAddress((void**)&q,    g_q);
        cudaGetSymbolAddress((void**)&k,    g_k);
        cudaGetSymbolAddress((void**)&v,    g_v);
        cudaGetSymbolAddress((void**)&u,    g_u);
        cudaGetSymbolAddress((void**)&pool, g_pool);
        cudaGetSymbolAddress((void**)&o1,   g_o1);
        cudaGetSymbolAddress((void**)&ffn,  g_ffn);
        cudaGetSymbolAddress((void**)&trig, g_trig);
        cudaGetSymbolAddress((void**)&wr,   g_wr);
        cudaFuncSetAttribute(attn_tc,    cudaFuncAttributeMaxDynamicSharedMemorySize, ATTN_SMEM);
        cudaFuncSetAttribute(proj4_tc,   cudaFuncAttributeMaxDynamicSharedMemorySize, GEMM_SMEM);
        cudaFuncSetAttribute(gemm_tc<1>, cudaFuncAttributeMaxDynamicSharedMemorySize, GEMM_SMEM);
        cudaFuncSetAttribute(gemm_tc<2>, cudaFuncAttributeMaxDynamicSharedMemorySize, GEMM_SMEM);
        cudaFuncSetAttribute(gemm_tc<3>, cudaFuncAttributeMaxDynamicSharedMemorySize, GEMM_SMEM);
    }

    // 0. round all weights to tf32 bit patterns (one pass each; correct bounds)
    cvtw_k<<<(WSZ/4 + 255)/256, 256>>>(wq,  wr + 0*(size_t)WSZ, WSZ/4);
    cvtw_k<<<(WSZ/4 + 255)/256, 256>>>(wk,  wr + 1*(size_t)WSZ, WSZ/4);
    cvtw_k<<<(WSZ/4 + 255)/256, 256>>>(wv,  wr + 2*(size_t)WSZ, WSZ/4);
    cvtw_k<<<(WSZ/4 + 255)/256, 256>>>(wu,  wr + 3*(size_t)WSZ, WSZ/4);
    cvtw_k<<<(WSZ/4 + 255)/256, 256>>>(wo,  wr + 4*(size_t)WSZ, WSZ/4);
    cvtw_k<<<(4*WSZ/4 + 255)/256, 256>>>(f1w, wr + 5*(size_t)WSZ, 4*WSZ/4);
    cvtw_k<<<(4*WSZ/4 + 255)/256, 256>>>(f2w, wr + 9*(size_t)WSZ, 4*WSZ/4);

    // 1. RMSNorm (z rounded)
    rmsnorm_k<<<Mr, 256>>>(x, rmsw, z);

    // 2. projections
    proj4_tc<<<dim3(Hh/128, Mr/128, 4), 256, GEMM_SMEM>>>(z, wr, q, k, v, u);

    // 3. RoPE
    sincos_k<<<(Tt*32 + 255)/256, 256>>>(trig);
    rope2_k<<<(2*Mr*512)/256, 256>>>(q, k, trig);

    // 4. attention -> pool
    attn_tc<<<dim3(Tt/64, Bb*NHh), 256, ATTN_SMEM>>>(q, k, v, rtab, pool);

    // 5. gated (rounded) -> z
    gate_k<<<(Mr*Hh/4)/256, 256>>>(u, pool, z);

    // 6. wo GEMM + residual mix -> o1 exact, pool rounded (pool is free now)
    gemm_tc<1><<<dim3(Hh/128, Mr/128), 256, GEMM_SMEM>>>(z, wr + 4*(size_t)WSZ, o1,
        Mr, Hh, Hh, nullptr, nullptr, x, gw, rw, pool);

    // 7. FFN1 + bias + gelu (rounded) -> ffn
    gemm_tc<2><<<dim3(FFN/128, Mr/128), 256, GEMM_SMEM>>>(pool, wr + 5*(size_t)WSZ, ffn,
        Mr, FFN, Hh, f1b, nullptr, nullptr, nullptr, nullptr, nullptr);

    // 8. FFN2 + bias + residual -> out
    gemm_tc<3><<<dim3(Hh/128, Mr/128), 256, GEMM_SMEM>>>(ffn, wr + 9*(size_t)WSZ, out,
        Mr, Hh, FFN, f2b, o1, nullptr, nullptr, nullptr, nullptr);
}

// round 11
// speedup vs baseline: 1.9897x; 1.8535x over previous
#include <cuda_runtime.h>
#include <cuda_fp16.h>
#include <math.h>
#include <stdint.h>

// Problem constants
#define Bb   2
#define Tt   2048
#define Hh   1024
#define NHh  16
#define Dd   64
#define Mr   (Bb*Tt)          // 4096 rows
#define FFN  (4*Hh)           // 4096
#define WSZ  (Hh*Hh)          // 1M elements

// ---------------- scratch (static device memory; no allocations) ----------------
__device__ __half g_zh [(size_t)Mr*Hh];   // rmsnorm out (half); reused for gated
__device__ __half g_qh [(size_t)Mr*Hh];
__device__ __half g_kh [(size_t)Mr*Hh];
__device__ __half g_vh [(size_t)Mr*Hh];
__device__ __half g_uh [(size_t)Mr*Hh];
__device__ __half g_ph [(size_t)Mr*Hh];   // attn pooled (half); reused as o1h
__device__ __half g_fh [(size_t)Mr*FFN];  // ffn intermediate (half)
__device__ __half g_wh [(size_t)13*WSZ];  // half weights: proj(4) | wo | f1w(4) | f2w(4)
__device__ float  g_o1 [(size_t)Mr*Hh];   // exact o1 (residual path)
__device__ float  g_trig[(size_t)Tt*32*2];

// ---------------- helpers ----------------
__device__ __forceinline__ void mma16(float& c0, float& c1, float& c2, float& c3,
                                      unsigned a0, unsigned a1, unsigned a2, unsigned a3,
                                      unsigned b0, unsigned b1) {
    asm("mma.sync.aligned.m16n8k16.row.col.f32.f16.f16.f32 "
        "{%0,%1,%2,%3}, {%4,%5,%6,%7}, {%8,%9}, {%0,%1,%2,%3};"
        : "+f"(c0), "+f"(c1), "+f"(c2), "+f"(c3)
        : "r"(a0), "r"(a1), "r"(a2), "r"(a3), "r"(b0), "r"(b1));
}
__device__ __forceinline__ unsigned h2u(__half2 h) { return *reinterpret_cast<unsigned*>(&h); }

// ---------------- weight rounding: all 13 WSZ in one launch ----------------
__global__ __launch_bounds__(256) void cvtall_k(
    const float* __restrict__ wq, const float* __restrict__ wk,
    const float* __restrict__ wv, const float* __restrict__ wu,
    const float* __restrict__ wo, const float* __restrict__ f1w,
    const float* __restrict__ f2w, __half* __restrict__ dst)
{
    const size_t Q = WSZ/4;
    size_t i = (size_t)blockIdx.x * 256 + threadIdx.x;
    if (i >= 13*Q) return;
    const float* src; size_t off;
    if (i < 5*Q) {
        int s = (int)(i / Q); off = i % Q;
        src = (s == 0) ? wq : (s == 1) ? wk : (s == 2) ? wv : (s == 3) ? wu : wo;
    } else if (i < 9*Q) { src = f1w; off = i - 5*Q; }
    else                { src = f2w; off = i - 9*Q; }
    float4 v = ((const float4*)src)[off];
    uint2 o;
    o.x = h2u(__floats2half2_rn(v.x, v.y));
    o.y = h2u(__floats2half2_rn(v.z, v.w));
    *(uint2*)(dst + i*4) = o;
}

// ---------------- RMSNorm (half output) ----------------
__global__ __launch_bounds__(256) void rmsnorm_k(const float* __restrict__ x,
                                                 const float* __restrict__ w,
                                                 __half* __restrict__ z) {
    int row = blockIdx.x;
    int t   = threadIdx.x;
    float4 v = ((const float4*)(x + (size_t)row * Hh))[t];
    float ss = v.x*v.x + v.y*v.y + v.z*v.z + v.w*v.w;
    #pragma unroll
    for (int o = 16; o; o >>= 1) ss += __shfl_xor_sync(0xffffffffu, ss, o);
    __shared__ float sred[8];
    if ((t & 31) == 0) sred[t >> 5] = ss;
    __syncthreads();
    if (t == 0) {
        float tot = 0.f;
        #pragma unroll
        for (int i = 0; i < 8; i++) tot += sred[i];
        sred[0] = rsqrtf(tot * (1.0f/Hh) + 1e-8f);
    }
    __syncthreads();
    float inv = sred[0];
    float4 wv = ((const float4*)w)[t];
    uint2 o;
    o.x = h2u(__floats2half2_rn(v.x*wv.x*inv, v.y*wv.y*inv));
    o.y = h2u(__floats2half2_rn(v.z*wv.z*inv, v.w*wv.w*inv));
    *(uint2*)(z + (size_t)row * Hh + t*4) = o;
}

// ================= fp16 m16n8k16 GEMM — R4-proven synchronous skeleton =================
// C = A[M,K] @ W[N,K]^T. Block 128x128, K-slab 32 (2 k16 steps), 8 warps (2Mx4N).
// EPI: 0 half store; 1 o1=sr*x+sg*acc (float) + half copy; 2 half gelu(acc+bias);
//      3 float acc+bias+resid
#define PKH 20   // uints (=half2) per smem row: 16 data + 4 pad

template<int EPI>
__device__ __forceinline__ void gemm_core(
    const __half* __restrict__ A, const __half* __restrict__ W,
    int M, int N, int K,
    __half* __restrict__ Ch, float* __restrict__ Cf,
    const float* __restrict__ bias, const float* __restrict__ resid,
    const float* __restrict__ xin,  const float* __restrict__ gw,
    const float* __restrict__ rw,   __half* __restrict__ C2h)
{
    __shared__ unsigned As[128*PKH];
    __shared__ unsigned Bs[128*PKH];

    const int tid  = threadIdx.x;
    const int lane = tid & 31, warp = tid >> 5;
    const int grp  = lane >> 2, tig = lane & 3;
    const int wm = warp & 1, wn = warp >> 1;
    const int m0 = blockIdx.y * 128, n0 = blockIdx.x * 128;

    const int lrow = tid >> 1;         // 0..127
    const int seg  = tid & 1;          // which 16-half segment of the 32-slab
    const __half* Ap = A + (size_t)(m0 + lrow) * K + seg*16;
    const __half* Wp = W + (size_t)(n0 + lrow) * K + seg*16;
    unsigned* Asl = As + lrow*PKH + seg*8;
    unsigned* Bsl = Bs + lrow*PKH + seg*8;

    float acc[4][4][4];
    #pragma unroll
    for (int a = 0; a < 4; a++)
        #pragma unroll
        for (int b = 0; b < 4; b++)
            #pragma unroll
            for (int c = 0; c < 4; c++) acc[a][b][c] = 0.f;

    for (int k0 = 0; k0 < K; k0 += 32) {
        uint4 a0 = *(const uint4*)(Ap + k0);
        uint4 a1 = *(const uint4*)(Ap + k0 + 8);
        uint4 b0 = *(const uint4*)(Wp + k0);
        uint4 b1 = *(const uint4*)(Wp + k0 + 8);
        __syncthreads();               // previous slab's compute done
        *(uint4*)(Asl)     = a0;
        *(uint4*)(Asl + 4) = a1;
        *(uint4*)(Bsl)     = b0;
        *(uint4*)(Bsl + 4) = b1;
        __syncthreads();

        #pragma unroll
        for (int s = 0; s < 2; s++) {  // two k16 steps per slab
            const int kb = s * 8;
            unsigned af[4][4], bf[4][2];
            #pragma unroll
            for (int tm = 0; tm < 4; tm++) {
                const int r = wm*64 + tm*16 + grp;
                af[tm][0] = As[r*PKH + kb + tig];
                af[tm][1] = As[(r+8)*PKH + kb + tig];
                af[tm][2] = As[r*PKH + kb + tig + 4];
                af[tm][3] = As[(r+8)*PKH + kb + tig + 4];
            }
            #pragma unroll
            for (int tn = 0; tn < 4; tn++) {
                const int n = wn*32 + tn*8 + grp;
                bf[tn][0] = Bs[n*PKH + kb + tig];
                bf[tn][1] = Bs[n*PKH + kb + tig + 4];
            }
            #pragma unroll
            for (int tm = 0; tm < 4; tm++)
                #pragma unroll
                for (int tn = 0; tn < 4; tn++)
                    mma16(acc[tm][tn][0], acc[tm][tn][1], acc[tm][tn][2], acc[tm][tn][3],
                          af[tm][0], af[tm][1], af[tm][2], af[tm][3],
                          bf[tn][0], bf[tn][1]);
        }
    }

    float sg = 0.f, sr = 0.f;
    if (EPI == 1) {
        sg = 1.f / (1.f + expf(-gw[0]));
        sr = 1.f / (1.f + expf(-rw[0]));
    }
    #pragma unroll
    for (int tm = 0; tm < 4; tm++) {
        #pragma unroll
        for (int tn = 0; tn < 4; tn++) {
            #pragma unroll
            for (int hc = 0; hc < 2; hc++) {        // c pairs (0,1) and (2,3)
                const int row = m0 + wm*64 + tm*16 + grp + hc*8;
                const int col = n0 + wn*32 + tn*8 + tig*2;
                const size_t idx = (size_t)row * N + col;
                float v0 = acc[tm][tn][hc*2 + 0];
                float v1 = acc[tm][tn][hc*2 + 1];
                if (EPI == 0) {
                    *(unsigned*)(Ch + idx) = h2u(__floats2half2_rn(v0, v1));
                } else if (EPI == 1) {
                    float o0 = sr * xin[idx]   + sg * v0;
                    float o1v = sr * xin[idx+1] + sg * v1;
                    Cf[idx]   = o0;
                    Cf[idx+1] = o1v;
                    *(unsigned*)(C2h + idx) = h2u(__floats2half2_rn(o0, o1v));
                } else if (EPI == 2) {
                    float g0 = v0 + bias[col];
                    float g1 = v1 + bias[col+1];
                    g0 = 0.5f * g0 * (1.f + erff(g0 * 0.70710678118654752f));
                    g1 = 0.5f * g1 * (1.f + erff(g1 * 0.70710678118654752f));
                    *(unsigned*)(Ch + idx) = h2u(__floats2half2_rn(g0, g1));
                } else {
                    Cf[idx]   = v0 + bias[col]   + resid[idx];
                    Cf[idx+1] = v1 + bias[col+1] + resid[idx+1];
                }
            }
        }
    }
}

template<int EPI>
__global__ __launch_bounds__(256) void gemm_tc(
    const __half* __restrict__ A, const __half* __restrict__ W,
    int M, int N, int K,
    __half* __restrict__ Ch, float* __restrict__ Cf,
    const float* __restrict__ bias, const float* __restrict__ resid,
    const float* __restrict__ xin,  const float* __restrict__ gw,
    const float* __restrict__ rw,   __half* __restrict__ C2h)
{
    gemm_core<EPI>(A, W, M, N, K, Ch, Cf, bias, resid, xin, gw, rw, C2h);
}

__global__ __launch_bounds__(256) void proj4_tc(
    const __half* __restrict__ A, const __half* __restrict__ Wh,
    __half* __restrict__ Cq, __half* __restrict__ Ck,
    __half* __restrict__ Cv, __half* __restrict__ Cu)
{
    const int which = blockIdx.z;
    const __half* W = Wh + (size_t)which * WSZ;
    __half* C = (which == 0) ? Cq : (which == 1) ? Ck : (which == 2) ? Cv : Cu;
    gemm_core<0>(A, W, Mr, Hh, Hh, C, nullptr, nullptr, nullptr, nullptr, nullptr, nullptr, nullptr);
}

// ---------------- RoPE ----------------
__global__ void sincos_k(float* __restrict__ trig) {
    int idx = blockIdx.x * blockDim.x + threadIdx.x;
    if (idx >= Tt * 32) return;
    int t = idx >> 5, i = idx & 31;
    double invf = exp(-((double)(2 * i) / 64.0) * log(10000.0));
    double ang  = (double)t * invf;
    double s, c;
    sincos(ang, &s, &c);
    trig[idx*2+0] = (float)c;
    trig[idx*2+1] = (float)s;
}

__global__ void rope2_k(__half* __restrict__ Q, __half* __restrict__ K,
                        const float* __restrict__ trig) {
    int idx = blockIdx.x * blockDim.x + threadIdx.x;   // 2*Mr*512 pairs
    __half* X = (idx < Mr*512) ? Q : K;
    int id2 = idx & (Mr*512 - 1);
    int m = id2 >> 9;
    int p = id2 & 511;
    int h = p >> 5, i = p & 31;
    int t = m & (Tt - 1);
    size_t off = (size_t)m * Hh + h * 64 + 2 * i;
    float c = trig[(t*32 + i)*2 + 0];
    float s = trig[(t*32 + i)*2 + 1];
    __half2* px = (__half2*)(X + off);
    float2 xv = __half22float2(*px);
    *px = __floats2half2_rn(xv.x * c - xv.y * s, xv.y * c + xv.x * s);
}

// ================= fp16 attention (R4-proven structure, half tiles, static smem) =================
// 64x64 tiles, warps 2Mx4N (warp tile 32x16), 4 k16-steps per tile GEMM.
#define PJH 36   // uints (half2) per smem row: 32 data + 4 pad
__global__ __launch_bounds__(256) void attn_tc(
    const __half* __restrict__ Qg, const __half* __restrict__ Kg,
    const __half* __restrict__ Vg, const float* __restrict__ rtab,
    __half* __restrict__ Og)
{
    __shared__ unsigned smu[4*64*PJH + 64*4 + 32];   // 38016 bytes
    unsigned* Qs = smu;                 // [i 64][d/2]
    unsigned* Ks = Qs + 64*PJH;         // [j 64][d/2]
    unsigned* Vt = Ks + 64*PJH;         // [d 64][j/2]
    unsigned* Ps = Vt + 64*PJH;         // [i 64][j/2]
    float*    red  = (float*)(Ps + 64*PJH);   // [64][4]
    float*    rabs = red + 64*4;              // [32]
    __half*   Vt_h = (__half*)Vt;

    const int tid  = threadIdx.x;
    const int lane = tid & 31, warp = tid >> 5;
    const int grp  = lane >> 2, tig = lane & 3;
    const int wm = warp & 1, wn = warp >> 1;
    const int i0 = blockIdx.x * 64;
    const int bh = blockIdx.y;
    const int b = bh >> 4, h = bh & 15;
    const size_t base = ((size_t)b * Tt) * Hh + (size_t)h * 64;

    if (tid < 32) rabs[tid] = rtab[tid];

    {   // Q tile: row r, 16-half chunk ch
        const int r = tid >> 2, ch = tid & 3;
        const uint4* src = (const uint4*)(Qg + base + (size_t)(i0 + r) * Hh + ch*16);
        uint4 q0 = src[0], q1 = src[1];
        *(uint4*)&Qs[r*PJH + ch*8]     = q0;
        *(uint4*)&Qs[r*PJH + ch*8 + 4] = q1;
    }

    float acc[2][2][4];
    #pragma unroll
    for (int a = 0; a < 2; a++)
        #pragma unroll
        for (int b2 = 0; b2 < 2; b2++)
            #pragma unroll
            for (int c = 0; c < 4; c++) acc[a][b2][c] = 0.f;
    float rsum[4] = {0.f, 0.f, 0.f, 0.f};
    const float scale = 0.125f;

    const int klr = tid >> 2, klc = tid & 3;          // K loader
    const int vlj = tid & 63, vld = (tid >> 6) * 16;  // V loader (transpose)

    for (int jt = 0; jt < Tt/64; jt++) {
        const int j0 = jt * 64;
        uint4 k0, k1, v0, v1;
        {
            const uint4* ksrc = (const uint4*)(Kg + base + (size_t)(j0 + klr) * Hh + klc*16);
            k0 = ksrc[0]; k1 = ksrc[1];
            const uint4* vsrc = (const uint4*)(Vg + base + (size_t)(j0 + vlj) * Hh + vld);
            v0 = vsrc[0]; v1 = vsrc[1];
        }
        __syncthreads();   // prev tile compute done with Ks/Vt/Ps
        *(uint4*)&Ks[klr*PJH + klc*8]     = k0;
        *(uint4*)&Ks[klr*PJH + klc*8 + 4] = k1;
        {   // transpose V: 16 halves (d = vld..vld+15) of row j -> Vt[d][j]
            unsigned vbuf[8] = {v0.x, v0.y, v0.z, v0.w, v1.x, v1.y, v1.z, v1.w};
            const __half* vp = (const __half*)vbuf;
            #pragma unroll
            for (int c = 0; c < 16; c++) {
                Vt_h[(vld + c) * (PJH*2) + vlj] = vp[c];
            }
        }
        __syncthreads();

        // S = Q K^T  (4 k16 steps over d)
        float s[2][2][4];
        #pragma unroll
        for (int a = 0; a < 2; a++)
            #pragma unroll
            for (int b2 = 0; b2 < 2; b2++)
                #pragma unroll
                for (int c = 0; c < 4; c++) s[a][b2][c] = 0.f;
        #pragma unroll
        for (int st = 0; st < 4; st++) {
            const int kb = st * 8;
            unsigned af[2][4], bf[2][2];
            #pragma unroll
            for (int tm = 0; tm < 2; tm++) {
                const int r = wm*32 + tm*16 + grp;
                af[tm][0] = Qs[r*PJH + kb + tig];
                af[tm][1] = Qs[(r+8)*PJH + kb + tig];
                af[tm][2] = Qs[r*PJH + kb + tig + 4];
                af[tm][3] = Qs[(r+8)*PJH + kb + tig + 4];
            }
            #pragma unroll
            for (int tn = 0; tn < 2; tn++) {
                const int n = wn*16 + tn*8 + grp;
                bf[tn][0] = Ks[n*PJH + kb + tig];
                bf[tn][1] = Ks[n*PJH + kb + tig + 4];
            }
            #pragma unroll
            for (int tm = 0; tm < 2; tm++)
                #pragma unroll
                for (int tn = 0; tn < 2; tn++)
                    mma16(s[tm][tn][0], s[tm][tn][1], s[tm][tn][2], s[tm][tn][3],
                          af[tm][0], af[tm][1], af[tm][2], af[tm][3],
                          bf[tn][0], bf[tn][1]);
        }

        // bias + clip + exp -> Ps (half2), rsum
        #pragma unroll
        for (int tm = 0; tm < 2; tm++) {
            #pragma unroll
            for (int hc = 0; hc < 2; hc++) {
                const int il = wm*32 + tm*16 + grp + hc*8;
                const int i  = i0 + il;
                #pragma unroll
                for (int tn = 0; tn < 2; tn++) {
                    const int jl0 = wn*16 + tn*8 + tig*2;
                    int rel0 = (j0 + jl0)     - i;
                    int rel1 = (j0 + jl0 + 1) - i;
                    rel0 = (rel0 < -16) ? -16 : (rel0 > 15 ? 15 : rel0);
                    rel1 = (rel1 < -16) ? -16 : (rel1 > 15 ? 15 : rel1);
                    float w0 = s[tm][tn][hc*2+0] * scale + rabs[rel0 + 16];
                    float w1 = s[tm][tn][hc*2+1] * scale + rabs[rel1 + 16];
                    w0 = fminf(fmaxf(w0, -50.f), 50.f);
                    w1 = fminf(fmaxf(w1, -50.f), 50.f);
                    float e0 = expf(w0), e1 = expf(w1);
                    rsum[tm*2 + hc] += e0 + e1;
                    Ps[il*PJH + (jl0 >> 1)] = h2u(__floats2half2_rn(e0, e1));
                }
            }
        }
        __syncthreads();

        // O += P V  (4 k16 steps over j)
        #pragma unroll
        for (int st = 0; st < 4; st++) {
            const int kb = st * 8;
            unsigned af[2][4], bf[2][2];
            #pragma unroll
            for (int tm = 0; tm < 2; tm++) {
                const int r = wm*32 + tm*16 + grp;
                af[tm][0] = Ps[r*PJH + kb + tig];
                af[tm][1] = Ps[(r+8)*PJH + kb + tig];
                af[tm][2] = Ps[r*PJH + kb + tig + 4];
                af[tm][3] = Ps[(r+8)*PJH + kb + tig + 4];
            }
            #pragma unroll
            for (int tn = 0; tn < 2; tn++) {
                const int n = wn*16 + tn*8 + grp;
                bf[tn][0] = Vt[n*PJH + kb + tig];
                bf[tn][1] = Vt[n*PJH + kb + tig + 4];
            }
            #pragma unroll
            for (int tm = 0; tm < 2; tm++)
                #pragma unroll
                for (int tn = 0; tn < 2; tn++)
                    mma16(acc[tm][tn][0], acc[tm][tn][1], acc[tm][tn][2], acc[tm][tn][3],
                          af[tm][0], af[tm][1], af[tm][2], af[tm][3],
                          bf[tn][0], bf[tn][1]);
        }
    }

    // row-sum reduce: tig lanes (shfl), then n-warps (smem)
    #pragma unroll
    for (int s2 = 0; s2 < 4; s2++) {
        float r = rsum[s2];
        r += __shfl_xor_sync(0xffffffffu, r, 1);
        r += __shfl_xor_sync(0xffffffffu, r, 2);
        if (tig == 0) {
            const int il = wm*32 + (s2 >> 1)*16 + grp + (s2 & 1)*8;
            red[il*4 + wn] = r;
        }
    }
    __syncthreads();

    #pragma unroll
    for (int tm = 0; tm < 2; tm++) {
        #pragma unroll
        for (int hc = 0; hc < 2; hc++) {
            const int il = wm*32 + tm*16 + grp + hc*8;
            float inv = 1.f / (red[il*4+0] + red[il*4+1] + red[il*4+2] + red[il*4+3]);
            #pragma unroll
            for (int tn = 0; tn < 2; tn++) {
                const int d0 = wn*16 + tn*8 + tig*2;
                float o0 = acc[tm][tn][hc*2+0] * inv;
                float o1 = acc[tm][tn][hc*2+1] * inv;
                *(unsigned*)(Og + base + (size_t)(i0 + il) * Hh + d0) =
                    h2u(__floats2half2_rn(o0, o1));
            }
        }
    }
}

// ---------------- gated = sigmoid(U) * pooled (half in/out) ----------------
__global__ void gate_k(const __half* __restrict__ U, const __half* __restrict__ P,
                       __half* __restrict__ G) {
    int i = blockIdx.x * blockDim.x + threadIdx.x;   // over Mr*Hh/4
    uint2 uu = *(const uint2*)(U + (size_t)i*4);
    uint2 pp = *(const uint2*)(P + (size_t)i*4);
    float2 u0 = __half22float2(*reinterpret_cast<__half2*>(&uu.x));
    float2 u1 = __half22float2(*reinterpret_cast<__half2*>(&uu.y));
    float2 p0 = __half22float2(*reinterpret_cast<__half2*>(&pp.x));
    float2 p1 = __half22float2(*reinterpret_cast<__half2*>(&pp.y));
    uint2 o;
    o.x = h2u(__floats2half2_rn(p0.x / (1.f + expf(-u0.x)), p0.y / (1.f + expf(-u0.y))));
    o.y = h2u(__floats2half2_rn(p1.x / (1.f + expf(-u1.x)), p1.y / (1.f + expf(-u1.y))));
    *(uint2*)(G + (size_t)i*4) = o;
}

// ---------------- launch ----------------
extern "C" void kernel_launch(void* const* d_in, const int* in_sizes, int n_in,
                              void* d_out, int out_size) {
    const float* x    = (const float*)d_in[0];
    // d_in[1] attn_mask: all-True, no-op. d_in[2] pos_ids: unused by reference rope.
    const float* wq   = (const float*)d_in[3];
    const float* wk   = (const float*)d_in[4];
    const float* wv   = (const float*)d_in[5];
    const float* wu   = (const float*)d_in[6];
    const float* wo   = (const float*)d_in[7];
    const float* f1w  = (const float*)d_in[8];
    const float* f1b  = (const float*)d_in[9];
    const float* f2w  = (const float*)d_in[10];
    const float* f2b  = (const float*)d_in[11];
    const float* rmsw = (const float*)d_in[12];
    const float* rtab = (const float*)d_in[13];
    const float* gw   = (const float*)d_in[14];
    const float* rw   = (const float*)d_in[15];
    float* out = (float*)d_out;

    static __half *zh = nullptr, *qh, *kh, *vh, *uh, *ph, *fh, *wh;
    static float *o1, *trig;
    if (!zh) {
        cudaGetSymbolAddress((void**)&zh,   g_zh);
        cudaGetSymbolAddress((void**)&qh,   g_qh);
        cudaGetSymbolAddress((void**)&kh,   g_kh);
        cudaGetSymbolAddress((void**)&vh,   g_vh);
        cudaGetSymbolAddress((void**)&uh,   g_uh);
        cudaGetSymbolAddress((void**)&ph,   g_ph);
        cudaGetSymbolAddress((void**)&fh,   g_fh);
        cudaGetSymbolAddress((void**)&wh,   g_wh);
        cudaGetSymbolAddress((void**)&o1,   g_o1);
        cudaGetSymbolAddress((void**)&trig, g_trig);
    }

    // 1. all weights -> half, one launch
    cvtall_k<<<(int)((13*(size_t)(WSZ/4) + 255)/256), 256>>>(wq, wk, wv, wu, wo, f1w, f2w, wh);

    // 2. RMSNorm -> zh (half)
    rmsnorm_k<<<Mr, 256>>>(x, rmsw, zh);

    // 3. trig table
    sincos_k<<<(Tt*32 + 255)/256, 256>>>(trig);

    // 4. projections -> qh,kh,vh,uh (half)
    proj4_tc<<<dim3(Hh/128, Mr/128, 4), 256>>>(zh, wh, qh, kh, vh, uh);

    // 5. RoPE on qh,kh
    rope2_k<<<(2*Mr*512)/256, 256>>>(qh, kh, trig);

    // 6. attention -> ph (half)
    attn_tc<<<dim3(Tt/64, Bb*NHh), 256>>>(qh, kh, vh, rtab, ph);

    // 7. gated = sigmoid(uh)*ph -> zh (half; zh free after proj)
    gate_k<<<(Mr*Hh/4)/256, 256>>>(uh, ph, zh);

    // 8. wo GEMM + residual mix -> o1 (float exact) + ph (half copy; ph free now)
    gemm_tc<1><<<dim3(Hh/128, Mr/128), 256>>>(zh, wh + 4*(size_t)WSZ,
        Mr, Hh, Hh, nullptr, o1, nullptr, nullptr, x, gw, rw, ph);

    // 9. FFN1 + bias + gelu -> fh (half)
    gemm_tc<2><<<dim3(FFN/128, Mr/128), 256>>>(ph, wh + 5*(size_t)WSZ,
        Mr, FFN, Hh, fh, nullptr, f1b, nullptr, nullptr, nullptr, nullptr, nullptr);

    // 10. FFN2 + bias + residual(o1) -> out (float)
    gemm_tc<3><<<dim3(Hh/128, Mr/128), 256>>>(fh, wh + 9*(size_t)WSZ,
        Mr, Hh, FFN, nullptr, out, f2b, o1, nullptr, nullptr, nullptr, nullptr);
}

// round 12
// speedup vs baseline: 1.9975x; 1.0039x over previous
#include <cuda_runtime.h>
#include <cuda_fp16.h>
#include <math.h>
#include <stdint.h>

// Problem constants
#define Bb   2
#define Tt   2048
#define Hh   1024
#define NHh  16
#define Dd   64
#define Mr   (Bb*Tt)          // 4096 rows
#define FFN  (4*Hh)           // 4096
#define WSZ  (Hh*Hh)          // 1M elements

// ---------------- scratch (static device memory; no allocations) ----------------
__device__ __half g_zh [(size_t)Mr*Hh];   // rmsnorm out (half); reused for gated
__device__ __half g_qh [(size_t)Mr*Hh];
__device__ __half g_kh [(size_t)Mr*Hh];
__device__ __half g_vh [(size_t)Mr*Hh];
__device__ __half g_uh [(size_t)Mr*Hh];
__device__ __half g_ph [(size_t)Mr*Hh];   // attn pooled (half); reused as o1h
__device__ __half g_fh [(size_t)Mr*FFN];  // ffn intermediate (half)
__device__ __half g_wh [(size_t)13*WSZ];  // half weights: proj(4) | wo | f1w(4) | f2w(4)
__device__ float  g_o1 [(size_t)Mr*Hh];   // exact o1 (residual path)
__device__ float  g_trig[(size_t)Tt*32*2];

// ---------------- helpers ----------------
__device__ __forceinline__ void mma16(float& c0, float& c1, float& c2, float& c3,
                                      unsigned a0, unsigned a1, unsigned a2, unsigned a3,
                                      unsigned b0, unsigned b1) {
    asm("mma.sync.aligned.m16n8k16.row.col.f32.f16.f16.f32 "
        "{%0,%1,%2,%3}, {%4,%5,%6,%7}, {%8,%9}, {%0,%1,%2,%3};"
        : "+f"(c0), "+f"(c1), "+f"(c2), "+f"(c3)
        : "r"(a0), "r"(a1), "r"(a2), "r"(a3), "r"(b0), "r"(b1));
}
__device__ __forceinline__ void ldsm4(unsigned& r0, unsigned& r1, unsigned& r2, unsigned& r3,
                                      const unsigned* p) {
    unsigned a = (unsigned)__cvta_generic_to_shared(p);
    asm volatile("ldmatrix.sync.aligned.m8n8.x4.shared.b16 {%0,%1,%2,%3}, [%4];"
        : "=r"(r0), "=r"(r1), "=r"(r2), "=r"(r3) : "r"(a));
}
__device__ __forceinline__ unsigned h2u(__half2 h) { return *reinterpret_cast<unsigned*>(&h); }

// ---------------- weight rounding: all 13 WSZ in one launch ----------------
__global__ __launch_bounds__(256) void cvtall_k(
    const float* __restrict__ wq, const float* __restrict__ wk,
    const float* __restrict__ wv, const float* __restrict__ wu,
    const float* __restrict__ wo, const float* __restrict__ f1w,
    const float* __restrict__ f2w, __half* __restrict__ dst)
{
    const size_t Q = WSZ/4;
    size_t i = (size_t)blockIdx.x * 256 + threadIdx.x;
    if (i >= 13*Q) return;
    const float* src; size_t off;
    if (i < 5*Q) {
        int s = (int)(i / Q); off = i % Q;
        src = (s == 0) ? wq : (s == 1) ? wk : (s == 2) ? wv : (s == 3) ? wu : wo;
    } else if (i < 9*Q) { src = f1w; off = i - 5*Q; }
    else                { src = f2w; off = i - 9*Q; }
    float4 v = ((const float4*)src)[off];
    uint2 o;
    o.x = h2u(__floats2half2_rn(v.x, v.y));
    o.y = h2u(__floats2half2_rn(v.z, v.w));
    *(uint2*)(dst + i*4) = o;
}

// ---------------- RMSNorm (half output) ----------------
__global__ __launch_bounds__(256) void rmsnorm_k(const float* __restrict__ x,
                                                 const float* __restrict__ w,
                                                 __half* __restrict__ z) {
    int row = blockIdx.x;
    int t   = threadIdx.x;
    float4 v = ((const float4*)(x + (size_t)row * Hh))[t];
    float ss = v.x*v.x + v.y*v.y + v.z*v.z + v.w*v.w;
    #pragma unroll
    for (int o = 16; o; o >>= 1) ss += __shfl_xor_sync(0xffffffffu, ss, o);
    __shared__ float sred[8];
    if ((t & 31) == 0) sred[t >> 5] = ss;
    __syncthreads();
    if (t == 0) {
        float tot = 0.f;
        #pragma unroll
        for (int i = 0; i < 8; i++) tot += sred[i];
        sred[0] = rsqrtf(tot * (1.0f/Hh) + 1e-8f);
    }
    __syncthreads();
    float inv = sred[0];
    float4 wv = ((const float4*)w)[t];
    uint2 o;
    o.x = h2u(__floats2half2_rn(v.x*wv.x*inv, v.y*wv.y*inv));
    o.y = h2u(__floats2half2_rn(v.z*wv.z*inv, v.w*wv.w*inv));
    *(uint2*)(z + (size_t)row * Hh + t*4) = o;
}

// ================= fp16 m16n8k16 GEMM, ldmatrix fragment loads =================
// C = A[M,K] @ W[N,K]^T. Block 128x128, K-slab 32 (2 k16 steps), 8 warps (2Mx4N).
// EPI: 0 half store; 1 o1=sr*x+sg*acc (float) + half copy; 2 half gelu(acc+bias);
//      3 float acc+bias+resid
#define PKH 20   // uints (=half2) per smem row: 16 data + 4 pad (conflict-free ldmatrix)

template<int EPI>
__device__ __forceinline__ void gemm_core(
    const __half* __restrict__ A, const __half* __restrict__ W,
    int M, int N, int K,
    __half* __restrict__ Ch, float* __restrict__ Cf,
    const float* __restrict__ bias, const float* __restrict__ resid,
    const float* __restrict__ xin,  const float* __restrict__ gw,
    const float* __restrict__ rw,   __half* __restrict__ C2h)
{
    __shared__ unsigned As[128*PKH];
    __shared__ unsigned Bs[128*PKH];

    const int tid  = threadIdx.x;
    const int lane = tid & 31, warp = tid >> 5;
    const int grp  = lane >> 2, tig = lane & 3;
    const int wm = warp & 1, wn = warp >> 1;
    const int m0 = blockIdx.y * 128, n0 = blockIdx.x * 128;

    const int lrow = tid >> 1;         // 0..127
    const int seg  = tid & 1;          // which 16-half segment of the 32-slab
    const __half* Ap = A + (size_t)(m0 + lrow) * K + seg*16;
    const __half* Wp = W + (size_t)(n0 + lrow) * K + seg*16;
    unsigned* Asl = As + lrow*PKH + seg*8;
    unsigned* Bsl = Bs + lrow*PKH + seg*8;

    // ldmatrix per-lane source offsets
    const int a_r  = (lane & 15);            // row within 16-row tile
    const int a_kh = ((lane >> 4) & 1) * 4;  // k-half (8 halves = 4 uints)
    const int b_r  = (lane & 7) + ((lane >> 4) & 1) * 8;   // n within 16-n pair
    const int b_kh = ((lane >> 3) & 1) * 4;

    float acc[4][4][4];
    #pragma unroll
    for (int a = 0; a < 4; a++)
        #pragma unroll
        for (int b = 0; b < 4; b++)
            #pragma unroll
            for (int c = 0; c < 4; c++) acc[a][b][c] = 0.f;

    for (int k0 = 0; k0 < K; k0 += 32) {
        uint4 a0 = *(const uint4*)(Ap + k0);
        uint4 a1 = *(const uint4*)(Ap + k0 + 8);
        uint4 b0 = *(const uint4*)(Wp + k0);
        uint4 b1 = *(const uint4*)(Wp + k0 + 8);
        __syncthreads();               // previous slab's compute done
        *(uint4*)(Asl)     = a0;
        *(uint4*)(Asl + 4) = a1;
        *(uint4*)(Bsl)     = b0;
        *(uint4*)(Bsl + 4) = b1;
        __syncthreads();

        #pragma unroll
        for (int s = 0; s < 2; s++) {  // two k16 steps per slab
            const int kb = s * 8;
            unsigned af[4][4], bf[4][2];
            #pragma unroll
            for (int tm = 0; tm < 4; tm++) {
                const int r = wm*64 + tm*16 + a_r;
                ldsm4(af[tm][0], af[tm][1], af[tm][2], af[tm][3],
                      As + r*PKH + kb + a_kh);
            }
            #pragma unroll
            for (int t2 = 0; t2 < 2; t2++) {
                const int n = wn*32 + t2*16 + b_r;
                ldsm4(bf[2*t2][0], bf[2*t2][1], bf[2*t2+1][0], bf[2*t2+1][1],
                      Bs + n*PKH + kb + b_kh);
            }
            #pragma unroll
            for (int tm = 0; tm < 4; tm++)
                #pragma unroll
                for (int tn = 0; tn < 4; tn++)
                    mma16(acc[tm][tn][0], acc[tm][tn][1], acc[tm][tn][2], acc[tm][tn][3],
                          af[tm][0], af[tm][1], af[tm][2], af[tm][3],
                          bf[tn][0], bf[tn][1]);
        }
    }

    float sg = 0.f, sr = 0.f;
    if (EPI == 1) {
        sg = 1.f / (1.f + expf(-gw[0]));
        sr = 1.f / (1.f + expf(-rw[0]));
    }
    #pragma unroll
    for (int tm = 0; tm < 4; tm++) {
        #pragma unroll
        for (int tn = 0; tn < 4; tn++) {
            #pragma unroll
            for (int hc = 0; hc < 2; hc++) {        // c pairs (0,1) and (2,3)
                const int row = m0 + wm*64 + tm*16 + grp + hc*8;
                const int col = n0 + wn*32 + tn*8 + tig*2;
                const size_t idx = (size_t)row * N + col;
                float v0 = acc[tm][tn][hc*2 + 0];
                float v1 = acc[tm][tn][hc*2 + 1];
                if (EPI == 0) {
                    *(unsigned*)(Ch + idx) = h2u(__floats2half2_rn(v0, v1));
                } else if (EPI == 1) {
                    float o0 = sr * xin[idx]   + sg * v0;
                    float o1v = sr * xin[idx+1] + sg * v1;
                    Cf[idx]   = o0;
                    Cf[idx+1] = o1v;
                    *(unsigned*)(C2h + idx) = h2u(__floats2half2_rn(o0, o1v));
                } else if (EPI == 2) {
                    float g0 = v0 + bias[col];
                    float g1 = v1 + bias[col+1];
                    g0 = 0.5f * g0 * (1.f + erff(g0 * 0.70710678118654752f));
                    g1 = 0.5f * g1 * (1.f + erff(g1 * 0.70710678118654752f));
                    *(unsigned*)(Ch + idx) = h2u(__floats2half2_rn(g0, g1));
                } else {
                    Cf[idx]   = v0 + bias[col]   + resid[idx];
                    Cf[idx+1] = v1 + bias[col+1] + resid[idx+1];
                }
            }
        }
    }
}

template<int EPI>
__global__ __launch_bounds__(256) void gemm_tc(
    const __half* __restrict__ A, const __half* __restrict__ W,
    int M, int N, int K,
    __half* __restrict__ Ch, float* __restrict__ Cf,
    const float* __restrict__ bias, const float* __restrict__ resid,
    const float* __restrict__ xin,  const float* __restrict__ gw,
    const float* __restrict__ rw,   __half* __restrict__ C2h)
{
    gemm_core<EPI>(A, W, M, N, K, Ch, Cf, bias, resid, xin, gw, rw, C2h);
}

__global__ __launch_bounds__(256) void proj4_tc(
    const __half* __restrict__ A, const __half* __restrict__ Wh,
    __half* __restrict__ Cq, __half* __restrict__ Ck,
    __half* __restrict__ Cv, __half* __restrict__ Cu)
{
    const int which = blockIdx.z;
    const __half* W = Wh + (size_t)which * WSZ;
    __half* C = (which == 0) ? Cq : (which == 1) ? Ck : (which == 2) ? Cv : Cu;
    gemm_core<0>(A, W, Mr, Hh, Hh, C, nullptr, nullptr, nullptr, nullptr, nullptr, nullptr, nullptr);
}

// ---------------- RoPE ----------------
__global__ void sincos_k(float* __restrict__ trig) {
    int idx = blockIdx.x * blockDim.x + threadIdx.x;
    if (idx >= Tt * 32) return;
    int t = idx >> 5, i = idx & 31;
    double invf = exp(-((double)(2 * i) / 64.0) * log(10000.0));
    double ang  = (double)t * invf;
    double s, c;
    sincos(ang, &s, &c);
    trig[idx*2+0] = (float)c;
    trig[idx*2+1] = (float)s;
}

__global__ void rope2_k(__half* __restrict__ Q, __half* __restrict__ K,
                        const float* __restrict__ trig) {
    int idx = blockIdx.x * blockDim.x + threadIdx.x;   // 2*Mr*512 pairs
    __half* X = (idx < Mr*512) ? Q : K;
    int id2 = idx & (Mr*512 - 1);
    int m = id2 >> 9;
    int p = id2 & 511;
    int h = p >> 5, i = p & 31;
    int t = m & (Tt - 1);
    size_t off = (size_t)m * Hh + h * 64 + 2 * i;
    float c = trig[(t*32 + i)*2 + 0];
    float s = trig[(t*32 + i)*2 + 1];
    __half2* px = (__half2*)(X + off);
    float2 xv = __half22float2(*px);
    *px = __floats2half2_rn(xv.x * c - xv.y * s, xv.y * c + xv.x * s);
}

// ================= fp16 attention (ldmatrix fragment loads) =================
// 64x64 tiles, warps 2Mx4N (warp tile 32x16), 4 k16-steps per tile GEMM.
#define PJH 36   // uints (half2) per smem row: 32 data + 4 pad (conflict-free ldmatrix)
__global__ __launch_bounds__(256) void attn_tc(
    const __half* __restrict__ Qg, const __half* __restrict__ Kg,
    const __half* __restrict__ Vg, const float* __restrict__ rtab,
    __half* __restrict__ Og)
{
    __shared__ unsigned smu[4*64*PJH + 64*4 + 32];   // 38016 bytes
    unsigned* Qs = smu;                 // [i 64][d/2]
    unsigned* Ks = Qs + 64*PJH;         // [j 64][d/2]
    unsigned* Vt = Ks + 64*PJH;         // [d 64][j/2]
    unsigned* Ps = Vt + 64*PJH;         // [i 64][j/2]
    float*    red  = (float*)(Ps + 64*PJH);   // [64][4]
    float*    rabs = red + 64*4;              // [32]
    __half*   Vt_h = (__half*)Vt;

    const int tid  = threadIdx.x;
    const int lane = tid & 31, warp = tid >> 5;
    const int grp  = lane >> 2, tig = lane & 3;
    const int wm = warp & 1, wn = warp >> 1;
    const int i0 = blockIdx.x * 64;
    const int bh = blockIdx.y;
    const int b = bh >> 4, h = bh & 15;
    const size_t base = ((size_t)b * Tt) * Hh + (size_t)h * 64;

    // ldmatrix per-lane offsets
    const int a_r  = (lane & 15);
    const int a_kh = ((lane >> 4) & 1) * 4;
    const int b_r  = (lane & 7) + ((lane >> 4) & 1) * 8;
    const int b_kh = ((lane >> 3) & 1) * 4;

    if (tid < 32) rabs[tid] = rtab[tid];

    {   // Q tile: row r, 16-half chunk ch
        const int r = tid >> 2, ch = tid & 3;
        const uint4* src = (const uint4*)(Qg + base + (size_t)(i0 + r) * Hh + ch*16);
        uint4 q0 = src[0], q1 = src[1];
        *(uint4*)&Qs[r*PJH + ch*8]     = q0;
        *(uint4*)&Qs[r*PJH + ch*8 + 4] = q1;
    }

    float acc[2][2][4];
    #pragma unroll
    for (int a = 0; a < 2; a++)
        #pragma unroll
        for (int b2 = 0; b2 < 2; b2++)
            #pragma unroll
            for (int c = 0; c < 4; c++) acc[a][b2][c] = 0.f;
    float rsum[4] = {0.f, 0.f, 0.f, 0.f};
    const float scale = 0.125f;

    const int klr = tid >> 2, klc = tid & 3;          // K loader
    const int vlj = tid & 63, vld = (tid >> 6) * 16;  // V loader (transpose)

    for (int jt = 0; jt < Tt/64; jt++) {
        const int j0 = jt * 64;
        uint4 k0, k1, v0, v1;
        {
            const uint4* ksrc = (const uint4*)(Kg + base + (size_t)(j0 + klr) * Hh + klc*16);
            k0 = ksrc[0]; k1 = ksrc[1];
            const uint4* vsrc = (const uint4*)(Vg + base + (size_t)(j0 + vlj) * Hh + vld);
            v0 = vsrc[0]; v1 = vsrc[1];
        }
        __syncthreads();   // prev tile compute done with Ks/Vt/Ps
        *(uint4*)&Ks[klr*PJH + klc*8]     = k0;
        *(uint4*)&Ks[klr*PJH + klc*8 + 4] = k1;
        {   // transpose V: 16 halves (d = vld..vld+15) of row j -> Vt[d][j]
            unsigned vbuf[8] = {v0.x, v0.y, v0.z, v0.w, v1.x, v1.y, v1.z, v1.w};
            const __half* vp = (const __half*)vbuf;
            #pragma unroll
            for (int c = 0; c < 16; c++) {
                Vt_h[(vld + c) * (PJH*2) + vlj] = vp[c];
            }
        }
        __syncthreads();

        // S = Q K^T  (4 k16 steps over d)
        float s[2][2][4];
        #pragma unroll
        for (int a = 0; a < 2; a++)
            #pragma unroll
            for (int b2 = 0; b2 < 2; b2++)
                #pragma unroll
                for (int c = 0; c < 4; c++) s[a][b2][c] = 0.f;
        #pragma unroll
        for (int st = 0; st < 4; st++) {
            const int kb = st * 8;
            unsigned af[2][4], bf[2][2];
            #pragma unroll
            for (int tm = 0; tm < 2; tm++) {
                const int r = wm*32 + tm*16 + a_r;
                ldsm4(af[tm][0], af[tm][1], af[tm][2], af[tm][3],
                      Qs + r*PJH + kb + a_kh);
            }
            {
                const int n = wn*16 + b_r;
                ldsm4(bf[0][0], bf[0][1], bf[1][0], bf[1][1],
                      Ks + n*PJH + kb + b_kh);
            }
            #pragma unroll
            for (int tm = 0; tm < 2; tm++)
                #pragma unroll
                for (int tn = 0; tn < 2; tn++)
                    mma16(s[tm][tn][0], s[tm][tn][1], s[tm][tn][2], s[tm][tn][3],
                          af[tm][0], af[tm][1], af[tm][2], af[tm][3],
                          bf[tn][0], bf[tn][1]);
        }

        // bias + clip + exp -> Ps (half2), rsum
        #pragma unroll
        for (int tm = 0; tm < 2; tm++) {
            #pragma unroll
            for (int hc = 0; hc < 2; hc++) {
                const int il = wm*32 + tm*16 + grp + hc*8;
                const int i  = i0 + il;
                #pragma unroll
                for (int tn = 0; tn < 2; tn++) {
                    const int jl0 = wn*16 + tn*8 + tig*2;
                    int rel0 = (j0 + jl0)     - i;
                    int rel1 = (j0 + jl0 + 1) - i;
                    rel0 = (rel0 < -16) ? -16 : (rel0 > 15 ? 15 : rel0);
                    rel1 = (rel1 < -16) ? -16 : (rel1 > 15 ? 15 : rel1);
                    float w0 = s[tm][tn][hc*2+0] * scale + rabs[rel0 + 16];
                    float w1 = s[tm][tn][hc*2+1] * scale + rabs[rel1 + 16];
                    w0 = fminf(fmaxf(w0, -50.f), 50.f);
                    w1 = fminf(fmaxf(w1, -50.f), 50.f);
                    float e0 = expf(w0), e1 = expf(w1);
                    rsum[tm*2 + hc] += e0 + e1;
                    Ps[il*PJH + (jl0 >> 1)] = h2u(__floats2half2_rn(e0, e1));
                }
            }
        }
        __syncthreads();

        // O += P V  (4 k16 steps over j)
        #pragma unroll
        for (int st = 0; st < 4; st++) {
            const int kb = st * 8;
            unsigned af[2][4], bf[2][2];
            #pragma unroll
            for (int tm = 0; tm < 2; tm++) {
                const int r = wm*32 + tm*16 + a_r;
                ldsm4(af[tm][0], af[tm][1], af[tm][2], af[tm][3],
                      Ps + r*PJH + kb + a_kh);
            }
            {
                const int n = wn*16 + b_r;
                ldsm4(bf[0][0], bf[0][1], bf[1][0], bf[1][1],
                      Vt + n*PJH + kb + b_kh);
            }
            #pragma unroll
            for (int tm = 0; tm < 2; tm++)
                #pragma unroll
                for (int tn = 0; tn < 2; tn++)
                    mma16(acc[tm][tn][0], acc[tm][tn][1], acc[tm][tn][2], acc[tm][tn][3],
                          af[tm][0], af[tm][1], af[tm][2], af[tm][3],
                          bf[tn][0], bf[tn][1]);
        }
    }

    // row-sum reduce: tig lanes (shfl), then n-warps (smem)
    #pragma unroll
    for (int s2 = 0; s2 < 4; s2++) {
        float r = rsum[s2];
        r += __shfl_xor_sync(0xffffffffu, r, 1);
        r += __shfl_xor_sync(0xffffffffu, r, 2);
        if (tig == 0) {
            const int il = wm*32 + (s2 >> 1)*16 + grp + (s2 & 1)*8;
            red[il*4 + wn] = r;
        }
    }
    __syncthreads();

    #pragma unroll
    for (int tm = 0; tm < 2; tm++) {
        #pragma unroll
        for (int hc = 0; hc < 2; hc++) {
            const int il = wm*32 + tm*16 + grp + hc*8;
            float inv = 1.f / (red[il*4+0] + red[il*4+1] + red[il*4+2] + red[il*4+3]);
            #pragma unroll
            for (int tn = 0; tn < 2; tn++) {
                const int d0 = wn*16 + tn*8 + tig*2;
                float o0 = acc[tm][tn][hc*2+0] * inv;
                float o1 = acc[tm][tn][hc*2+1] * inv;
                *(unsigned*)(Og + base + (size_t)(i0 + il) * Hh + d0) =
                    h2u(__floats2half2_rn(o0, o1));
            }
        }
    }
}

// ---------------- gated = sigmoid(U) * pooled (half in/out) ----------------
__global__ void gate_k(const __half* __restrict__ U, const __half* __restrict__ P,
                       __half* __restrict__ G) {
    int i = blockIdx.x * blockDim.x + threadIdx.x;   // over Mr*Hh/4
    uint2 uu = *(const uint2*)(U + (size_t)i*4);
    uint2 pp = *(const uint2*)(P + (size_t)i*4);
    float2 u0 = __half22float2(*reinterpret_cast<__half2*>(&uu.x));
    float2 u1 = __half22float2(*reinterpret_cast<__half2*>(&uu.y));
    float2 p0 = __half22float2(*reinterpret_cast<__half2*>(&pp.x));
    float2 p1 = __half22float2(*reinterpret_cast<__half2*>(&pp.y));
    uint2 o;
    o.x = h2u(__floats2half2_rn(p0.x / (1.f + expf(-u0.x)), p0.y / (1.f + expf(-u0.y))));
    o.y = h2u(__floats2half2_rn(p1.x / (1.f + expf(-u1.x)), p1.y / (1.f + expf(-u1.y))));
    *(uint2*)(G + (size_t)i*4) = o;
}

// ---------------- launch ----------------
extern "C" void kernel_launch(void* const* d_in, const int* in_sizes, int n_in,
                              void* d_out, int out_size) {
    const float* x    = (const float*)d_in[0];
    // d_in[1] attn_mask: all-True, no-op. d_in[2] pos_ids: unused by reference rope.
    const float* wq   = (const float*)d_in[3];
    const float* wk   = (const float*)d_in[4];
    const float* wv   = (const float*)d_in[5];
    const float* wu   = (const float*)d_in[6];
    const float* wo   = (const float*)d_in[7];
    const float* f1w  = (const float*)d_in[8];
    const float* f1b  = (const float*)d_in[9];
    const float* f2w  = (const float*)d_in[10];
    const float* f2b  = (const float*)d_in[11];
    const float* rmsw = (const float*)d_in[12];
    const float* rtab = (const float*)d_in[13];
    const float* gw   = (const float*)d_in[14];
    const float* rw   = (const float*)d_in[15];
    float* out = (float*)d_out;

    static __half *zh = nullptr, *qh, *kh, *vh, *uh, *ph, *fh, *wh;
    static float *o1, *trig;
    if (!zh) {
        cudaGetSymbolAddress((void**)&zh,   g_zh);
        cudaGetSymbolAddress((void**)&qh,   g_qh);
        cudaGetSymbolAddress((void**)&kh,   g_kh);
        cudaGetSymbolAddress((void**)&vh,   g_vh);
        cudaGetSymbolAddress((void**)&uh,   g_uh);
        cudaGetSymbolAddress((void**)&ph,   g_ph);
        cudaGetSymbolAddress((void**)&fh,   g_fh);
        cudaGetSymbolAddress((void**)&wh,   g_wh);
        cudaGetSymbolAddress((void**)&o1,   g_o1);
        cudaGetSymbolAddress((void**)&trig, g_trig);
    }

    // 1. all weights -> half, one launch
    cvtall_k<<<(int)((13*(size_t)(WSZ/4) + 255)/256), 256>>>(wq, wk, wv, wu, wo, f1w, f2w, wh);

    // 2. RMSNorm -> zh (half)
    rmsnorm_k<<<Mr, 256>>>(x, rmsw, zh);

    // 3. trig table
    sincos_k<<<(Tt*32 + 255)/256, 256>>>(trig);

    // 4. projections -> qh,kh,vh,uh (half)   [ncu capture slot]
    proj4_tc<<<dim3(Hh/128, Mr/128, 4), 256>>>(zh, wh, qh, kh, vh, uh);

    // 5. RoPE on qh,kh
    rope2_k<<<(2*Mr*512)/256, 256>>>(qh, kh, trig);

    // 6. attention -> ph (half)
    attn_tc<<<dim3(Tt/64, Bb*NHh), 256>>>(qh, kh, vh, rtab, ph);

    // 7. gated = sigmoid(uh)*ph -> zh (half; zh free after proj)
    gate_k<<<(Mr*Hh/4)/256, 256>>>(uh, ph, zh);

    // 8. wo GEMM + residual mix -> o1 (float exact) + ph (half copy; ph free now)
    gemm_tc<1><<<dim3(Hh/128, Mr/128), 256>>>(zh, wh + 4*(size_t)WSZ,
        Mr, Hh, Hh, nullptr, o1, nullptr, nullptr, x, gw, rw, ph);

    // 9. FFN1 + bias + gelu -> fh (half)
    gemm_tc<2><<<dim3(FFN/128, Mr/128), 256>>>(ph, wh + 5*(size_t)WSZ,
        Mr, FFN, Hh, fh, nullptr, f1b, nullptr, nullptr, nullptr, nullptr, nullptr);

    // 10. FFN2 + bias + residual(o1) -> out (float)
    gemm_tc<3><<<dim3(Hh/128, Mr/128), 256>>>(fh, wh + 9*(size_t)WSZ,
        Mr, Hh, FFN, nullptr, out, f2b, o1, nullptr, nullptr, nullptr, nullptr);
}

// round 13
// speedup vs baseline: 2.1012x; 1.0520x over previous
#include <cuda_runtime.h>
#include <cuda_fp16.h>
#include <math.h>
#include <stdint.h>

// Problem constants
#define Bb   2
#define Tt   2048
#define Hh   1024
#define NHh  16
#define Dd   64
#define Mr   (Bb*Tt)          // 4096 rows
#define FFN  (4*Hh)           // 4096
#define WSZ  (Hh*Hh)          // 1M elements

// ---------------- scratch (static device memory; no allocations) ----------------
__device__ __half g_zh [(size_t)Mr*Hh];   // rmsnorm out (half); reused for gated
__device__ __half g_qh [(size_t)Mr*Hh];
__device__ __half g_kh [(size_t)Mr*Hh];
__device__ __half g_vh [(size_t)Mr*Hh];
__device__ __half g_uh [(size_t)Mr*Hh];
__device__ __half g_ph [(size_t)Mr*Hh];   // attn pooled (half); reused as o1h
__device__ __half g_fh [(size_t)Mr*FFN];  // ffn intermediate (half)
__device__ __half g_wh [(size_t)13*WSZ];  // half weights: proj(4) | wo | f1w(4) | f2w(4)
__device__ float  g_o1 [(size_t)Mr*Hh];   // exact o1 (residual path)
__device__ float  g_trig[(size_t)Tt*32*2];

// ---------------- helpers ----------------
__device__ __forceinline__ void mma16(float& c0, float& c1, float& c2, float& c3,
                                      unsigned a0, unsigned a1, unsigned a2, unsigned a3,
                                      unsigned b0, unsigned b1) {
    asm("mma.sync.aligned.m16n8k16.row.col.f32.f16.f16.f32 "
        "{%0,%1,%2,%3}, {%4,%5,%6,%7}, {%8,%9}, {%0,%1,%2,%3};"
        : "+f"(c0), "+f"(c1), "+f"(c2), "+f"(c3)
        : "r"(a0), "r"(a1), "r"(a2), "r"(a3), "r"(b0), "r"(b1));
}
__device__ __forceinline__ void ldsm4(unsigned& r0, unsigned& r1, unsigned& r2, unsigned& r3,
                                      const unsigned* p) {
    unsigned a = (unsigned)__cvta_generic_to_shared(p);
    asm volatile("ldmatrix.sync.aligned.m8n8.x4.shared.b16 {%0,%1,%2,%3}, [%4];"
        : "=r"(r0), "=r"(r1), "=r"(r2), "=r"(r3) : "r"(a));
}
__device__ __forceinline__ unsigned h2u(__half2 h) { return *reinterpret_cast<unsigned*>(&h); }

// ---------------- weight rounding: all 13 WSZ in one launch ----------------
__global__ __launch_bounds__(256) void cvtall_k(
    const float* __restrict__ wq, const float* __restrict__ wk,
    const float* __restrict__ wv, const float* __restrict__ wu,
    const float* __restrict__ wo, const float* __restrict__ f1w,
    const float* __restrict__ f2w, __half* __restrict__ dst)
{
    const size_t Q = WSZ/4;
    size_t i = (size_t)blockIdx.x * 256 + threadIdx.x;
    if (i >= 13*Q) return;
    const float* src; size_t off;
    if (i < 5*Q) {
        int s = (int)(i / Q); off = i % Q;
        src = (s == 0) ? wq : (s == 1) ? wk : (s == 2) ? wv : (s == 3) ? wu : wo;
    } else if (i < 9*Q) { src = f1w; off = i - 5*Q; }
    else                { src = f2w; off = i - 9*Q; }
    float4 v = ((const float4*)src)[off];
    uint2 o;
    o.x = h2u(__floats2half2_rn(v.x, v.y));
    o.y = h2u(__floats2half2_rn(v.z, v.w));
    *(uint2*)(dst + i*4) = o;
}

// ---------------- RMSNorm (half output) ----------------
__global__ __launch_bounds__(256) void rmsnorm_k(const float* __restrict__ x,
                                                 const float* __restrict__ w,
                                                 __half* __restrict__ z) {
    int row = blockIdx.x;
    int t   = threadIdx.x;
    float4 v = ((const float4*)(x + (size_t)row * Hh))[t];
    float ss = v.x*v.x + v.y*v.y + v.z*v.z + v.w*v.w;
    #pragma unroll
    for (int o = 16; o; o >>= 1) ss += __shfl_xor_sync(0xffffffffu, ss, o);
    __shared__ float sred[8];
    if ((t & 31) == 0) sred[t >> 5] = ss;
    __syncthreads();
    if (t == 0) {
        float tot = 0.f;
        #pragma unroll
        for (int i = 0; i < 8; i++) tot += sred[i];
        sred[0] = rsqrtf(tot * (1.0f/Hh) + 1e-8f);
    }
    __syncthreads();
    float inv = sred[0];
    float4 wv = ((const float4*)w)[t];
    uint2 o;
    o.x = h2u(__floats2half2_rn(v.x*wv.x*inv, v.y*wv.y*inv));
    o.y = h2u(__floats2half2_rn(v.z*wv.z*inv, v.w*wv.w*inv));
    *(uint2*)(z + (size_t)row * Hh + t*4) = o;
}

// ================= fp16 m16n8k16 GEMM, 64x64 warp tiles =================
// C = A[M,K] @ W[N,K]^T. Block 128x128, 4 warps (2Mx2N, warp tile 64x64),
// K-slab 32 (2 k16 steps). 128 threads.
// EPI: 0 half store; 1 o1=sr*x+sg*acc (float) + half copy; 2 half gelu(acc+bias);
//      3 float acc+bias+resid
#define PKH 20   // uints (=half2) per smem row: 16 data + 4 pad (conflict-free ldmatrix)

template<int EPI>
__device__ __forceinline__ void gemm_core(
    const __half* __restrict__ A, const __half* __restrict__ W,
    int M, int N, int K,
    __half* __restrict__ Ch, float* __restrict__ Cf,
    const float* __restrict__ bias, const float* __restrict__ resid,
    const float* __restrict__ xin,  const float* __restrict__ gw,
    const float* __restrict__ rw,   __half* __restrict__ C2h)
{
    __shared__ unsigned As[128*PKH];
    __shared__ unsigned Bs[128*PKH];

    const int tid  = threadIdx.x;              // 128 threads
    const int lane = tid & 31, warp = tid >> 5;
    const int grp  = lane >> 2, tig = lane & 3;
    const int wm = warp & 1, wn = warp >> 1;   // 2 x 2 warps, tile 64x64
    const int m0 = blockIdx.y * 128, n0 = blockIdx.x * 128;

    // loader: 2 threads per row, 2 passes of 64 rows (keeps R12's coalescing)
    const int lrow = tid >> 1;         // 0..63 (+64 on pass 1)
    const int seg  = tid & 1;          // which 16-half segment of the 32-slab
    const __half* Ap = A + (size_t)(m0 + lrow) * K + seg*16;
    const __half* Wp = W + (size_t)(n0 + lrow) * K + seg*16;
    const size_t rstep = (size_t)64 * K;
    unsigned* Asl = As + lrow*PKH + seg*8;
    unsigned* Bsl = Bs + lrow*PKH + seg*8;

    // ldmatrix per-lane source offsets
    const int a_r  = (lane & 15);            // row within 16-row tile
    const int a_kh = ((lane >> 4) & 1) * 4;  // k-half (8 halves = 4 uints)
    const int b_r  = (lane & 7) + ((lane >> 4) & 1) * 8;   // n within 16-n pair
    const int b_kh = ((lane >> 3) & 1) * 4;

    float acc[4][8][4];
    #pragma unroll
    for (int a = 0; a < 4; a++)
        #pragma unroll
        for (int b = 0; b < 8; b++)
            #pragma unroll
            for (int c = 0; c < 4; c++) acc[a][b][c] = 0.f;

    for (int k0 = 0; k0 < K; k0 += 32) {
        uint4 a0 = *(const uint4*)(Ap + k0);
        uint4 a1 = *(const uint4*)(Ap + k0 + 8);
        uint4 a2 = *(const uint4*)(Ap + rstep + k0);
        uint4 a3 = *(const uint4*)(Ap + rstep + k0 + 8);
        uint4 b0 = *(const uint4*)(Wp + k0);
        uint4 b1 = *(const uint4*)(Wp + k0 + 8);
        uint4 b2 = *(const uint4*)(Wp + rstep + k0);
        uint4 b3 = *(const uint4*)(Wp + rstep + k0 + 8);
        __syncthreads();               // previous slab's compute done
        *(uint4*)(Asl)               = a0;
        *(uint4*)(Asl + 4)           = a1;
        *(uint4*)(Asl + 64*PKH)      = a2;
        *(uint4*)(Asl + 64*PKH + 4)  = a3;
        *(uint4*)(Bsl)               = b0;
        *(uint4*)(Bsl + 4)           = b1;
        *(uint4*)(Bsl + 64*PKH)      = b2;
        *(uint4*)(Bsl + 64*PKH + 4)  = b3;
        __syncthreads();

        #pragma unroll
        for (int s = 0; s < 2; s++) {  // two k16 steps per slab
            const int kb = s * 8;
            unsigned af[4][4], bf[8][2];
            #pragma unroll
            for (int tm = 0; tm < 4; tm++) {
                const int r = wm*64 + tm*16 + a_r;
                ldsm4(af[tm][0], af[tm][1], af[tm][2], af[tm][3],
                      As + r*PKH + kb + a_kh);
            }
            #pragma unroll
            for (int t2 = 0; t2 < 4; t2++) {
                const int n = wn*64 + t2*16 + b_r;
                ldsm4(bf[2*t2][0], bf[2*t2][1], bf[2*t2+1][0], bf[2*t2+1][1],
                      Bs + n*PKH + kb + b_kh);
            }
            #pragma unroll
            for (int tm = 0; tm < 4; tm++)
                #pragma unroll
                for (int tn = 0; tn < 8; tn++)
                    mma16(acc[tm][tn][0], acc[tm][tn][1], acc[tm][tn][2], acc[tm][tn][3],
                          af[tm][0], af[tm][1], af[tm][2], af[tm][3],
                          bf[tn][0], bf[tn][1]);
        }
    }

    float sg = 0.f, sr = 0.f;
    if (EPI == 1) {
        sg = 1.f / (1.f + expf(-gw[0]));
        sr = 1.f / (1.f + expf(-rw[0]));
    }
    #pragma unroll
    for (int tm = 0; tm < 4; tm++) {
        #pragma unroll
        for (int tn = 0; tn < 8; tn++) {
            #pragma unroll
            for (int hc = 0; hc < 2; hc++) {        // c pairs (0,1) and (2,3)
                const int row = m0 + wm*64 + tm*16 + grp + hc*8;
                const int col = n0 + wn*64 + tn*8 + tig*2;
                const size_t idx = (size_t)row * N + col;
                float v0 = acc[tm][tn][hc*2 + 0];
                float v1 = acc[tm][tn][hc*2 + 1];
                if (EPI == 0) {
                    *(unsigned*)(Ch + idx) = h2u(__floats2half2_rn(v0, v1));
                } else if (EPI == 1) {
                    float o0 = sr * xin[idx]   + sg * v0;
                    float o1v = sr * xin[idx+1] + sg * v1;
                    Cf[idx]   = o0;
                    Cf[idx+1] = o1v;
                    *(unsigned*)(C2h + idx) = h2u(__floats2half2_rn(o0, o1v));
                } else if (EPI == 2) {
                    float g0 = v0 + bias[col];
                    float g1 = v1 + bias[col+1];
                    g0 = 0.5f * g0 * (1.f + erff(g0 * 0.70710678118654752f));
                    g1 = 0.5f * g1 * (1.f + erff(g1 * 0.70710678118654752f));
                    *(unsigned*)(Ch + idx) = h2u(__floats2half2_rn(g0, g1));
                } else {
                    Cf[idx]   = v0 + bias[col]   + resid[idx];
                    Cf[idx+1] = v1 + bias[col+1] + resid[idx+1];
                }
            }
        }
    }
}

template<int EPI>
__global__ __launch_bounds__(128, 2) void gemm_tc(
    const __half* __restrict__ A, const __half* __restrict__ W,
    int M, int N, int K,
    __half* __restrict__ Ch, float* __restrict__ Cf,
    const float* __restrict__ bias, const float* __restrict__ resid,
    const float* __restrict__ xin,  const float* __restrict__ gw,
    const float* __restrict__ rw,   __half* __restrict__ C2h)
{
    gemm_core<EPI>(A, W, M, N, K, Ch, Cf, bias, resid, xin, gw, rw, C2h);
}

__global__ __launch_bounds__(128, 2) void proj4_tc(
    const __half* __restrict__ A, const __half* __restrict__ Wh,
    __half* __restrict__ Cq, __half* __restrict__ Ck,
    __half* __restrict__ Cv, __half* __restrict__ Cu)
{
    const int which = blockIdx.z;
    const __half* W = Wh + (size_t)which * WSZ;
    __half* C = (which == 0) ? Cq : (which == 1) ? Ck : (which == 2) ? Cv : Cu;
    gemm_core<0>(A, W, Mr, Hh, Hh, C, nullptr, nullptr, nullptr, nullptr, nullptr, nullptr, nullptr);
}

// ---------------- RoPE ----------------
__global__ void sincos_k(float* __restrict__ trig) {
    int idx = blockIdx.x * blockDim.x + threadIdx.x;
    if (idx >= Tt * 32) return;
    int t = idx >> 5, i = idx & 31;
    double invf = exp(-((double)(2 * i) / 64.0) * log(10000.0));
    double ang  = (double)t * invf;
    double s, c;
    sincos(ang, &s, &c);
    trig[idx*2+0] = (float)c;
    trig[idx*2+1] = (float)s;
}

__global__ void rope2_k(__half* __restrict__ Q, __half* __restrict__ K,
                        const float* __restrict__ trig) {
    int idx = blockIdx.x * blockDim.x + threadIdx.x;   // 2*Mr*512 pairs
    __half* X = (idx < Mr*512) ? Q : K;
    int id2 = idx & (Mr*512 - 1);
    int m = id2 >> 9;
    int p = id2 & 511;
    int h = p >> 5, i = p & 31;
    int t = m & (Tt - 1);
    size_t off = (size_t)m * Hh + h * 64 + 2 * i;
    float c = trig[(t*32 + i)*2 + 0];
    float s = trig[(t*32 + i)*2 + 1];
    __half2* px = (__half2*)(X + off);
    float2 xv = __half22float2(*px);
    *px = __floats2half2_rn(xv.x * c - xv.y * s, xv.y * c + xv.x * s);
}

// ================= fp16 attention (ldmatrix fragment loads) — unchanged from R12 =================
#define PJH 36   // uints (half2) per smem row: 32 data + 4 pad (conflict-free ldmatrix)
__global__ __launch_bounds__(256) void attn_tc(
    const __half* __restrict__ Qg, const __half* __restrict__ Kg,
    const __half* __restrict__ Vg, const float* __restrict__ rtab,
    __half* __restrict__ Og)
{
    __shared__ unsigned smu[4*64*PJH + 64*4 + 32];   // 38016 bytes
    unsigned* Qs = smu;                 // [i 64][d/2]
    unsigned* Ks = Qs + 64*PJH;         // [j 64][d/2]
    unsigned* Vt = Ks + 64*PJH;         // [d 64][j/2]
    unsigned* Ps = Vt + 64*PJH;         // [i 64][j/2]
    float*    red  = (float*)(Ps + 64*PJH);   // [64][4]
    float*    rabs = red + 64*4;              // [32]
    __half*   Vt_h = (__half*)Vt;

    const int tid  = threadIdx.x;
    const int lane = tid & 31, warp = tid >> 5;
    const int grp  = lane >> 2, tig = lane & 3;
    const int wm = warp & 1, wn = warp >> 1;
    const int i0 = blockIdx.x * 64;
    const int bh = blockIdx.y;
    const int b = bh >> 4, h = bh & 15;
    const size_t base = ((size_t)b * Tt) * Hh + (size_t)h * 64;

    const int a_r  = (lane & 15);
    const int a_kh = ((lane >> 4) & 1) * 4;
    const int b_r  = (lane & 7) + ((lane >> 4) & 1) * 8;
    const int b_kh = ((lane >> 3) & 1) * 4;

    if (tid < 32) rabs[tid] = rtab[tid];

    {   // Q tile: row r, 16-half chunk ch
        const int r = tid >> 2, ch = tid & 3;
        const uint4* src = (const uint4*)(Qg + base + (size_t)(i0 + r) * Hh + ch*16);
        uint4 q0 = src[0], q1 = src[1];
        *(uint4*)&Qs[r*PJH + ch*8]     = q0;
        *(uint4*)&Qs[r*PJH + ch*8 + 4] = q1;
    }

    float acc[2][2][4];
    #pragma unroll
    for (int a = 0; a < 2; a++)
        #pragma unroll
        for (int b2 = 0; b2 < 2; b2++)
            #pragma unroll
            for (int c = 0; c < 4; c++) acc[a][b2][c] = 0.f;
    float rsum[4] = {0.f, 0.f, 0.f, 0.f};
    const float scale = 0.125f;

    const int klr = tid >> 2, klc = tid & 3;          // K loader
    const int vlj = tid & 63, vld = (tid >> 6) * 16;  // V loader (transpose)

    for (int jt = 0; jt < Tt/64; jt++) {
        const int j0 = jt * 64;
        uint4 k0, k1, v0, v1;
        {
            const uint4* ksrc = (const uint4*)(Kg + base + (size_t)(j0 + klr) * Hh + klc*16);
            k0 = ksrc[0]; k1 = ksrc[1];
            const uint4* vsrc = (const uint4*)(Vg + base + (size_t)(j0 + vlj) * Hh + vld);
            v0 = vsrc[0]; v1 = vsrc[1];
        }
        __syncthreads();   // prev tile compute done with Ks/Vt/Ps
        *(uint4*)&Ks[klr*PJH + klc*8]     = k0;
        *(uint4*)&Ks[klr*PJH + klc*8 + 4] = k1;
        {   // transpose V: 16 halves (d = vld..vld+15) of row j -> Vt[d][j]
            unsigned vbuf[8] = {v0.x, v0.y, v0.z, v0.w, v1.x, v1.y, v1.z, v1.w};
            const __half* vp = (const __half*)vbuf;
            #pragma unroll
            for (int c = 0; c < 16; c++) {
                Vt_h[(vld + c) * (PJH*2) + vlj] = vp[c];
            }
        }
        __syncthreads();

        // S = Q K^T  (4 k16 steps over d)
        float s[2][2][4];
        #pragma unroll
        for (int a = 0; a < 2; a++)
            #pragma unroll
            for (int b2 = 0; b2 < 2; b2++)
                #pragma unroll
                for (int c = 0; c < 4; c++) s[a][b2][c] = 0.f;
        #pragma unroll
        for (int st = 0; st < 4; st++) {
            const int kb = st * 8;
            unsigned af[2][4], bf[2][2];
            #pragma unroll
            for (int tm = 0; tm < 2; tm++) {
                const int r = wm*32 + tm*16 + a_r;
                ldsm4(af[tm][0], af[tm][1], af[tm][2], af[tm][3],
                      Qs + r*PJH + kb + a_kh);
            }
            {
                const int n = wn*16 + b_r;
                ldsm4(bf[0][0], bf[0][1], bf[1][0], bf[1][1],
                      Ks + n*PJH + kb + b_kh);
            }
            #pragma unroll
            for (int tm = 0; tm < 2; tm++)
                #pragma unroll
                for (int tn = 0; tn < 2; tn++)
                    mma16(s[tm][tn][0], s[tm][tn][1], s[tm][tn][2], s[tm][tn][3],
                          af[tm][0], af[tm][1], af[tm][2], af[tm][3],
                          bf[tn][0], bf[tn][1]);
        }

        // bias + clip + exp -> Ps (half2), rsum
        #pragma unroll
        for (int tm = 0; tm < 2; tm++) {
            #pragma unroll
            for (int hc = 0; hc < 2; hc++) {
                const int il = wm*32 + tm*16 + grp + hc*8;
                const int i  = i0 + il;
                #pragma unroll
                for (int tn = 0; tn < 2; tn++) {
                    const int jl0 = wn*16 + tn*8 + tig*2;
                    int rel0 = (j0 + jl0)     - i;
                    int rel1 = (j0 + jl0 + 1) - i;
                    rel0 = (rel0 < -16) ? -16 : (rel0 > 15 ? 15 : rel0);
                    rel1 = (rel1 < -16) ? -16 : (rel1 > 15 ? 15 : rel1);
                    float w0 = s[tm][tn][hc*2+0] * scale + rabs[rel0 + 16];
                    float w1 = s[tm][tn][hc*2+1] * scale + rabs[rel1 + 16];
                    w0 = fminf(fmaxf(w0, -50.f), 50.f);
                    w1 = fminf(fmaxf(w1, -50.f), 50.f);
                    float e0 = expf(w0), e1 = expf(w1);
                    rsum[tm*2 + hc] += e0 + e1;
                    Ps[il*PJH + (jl0 >> 1)] = h2u(__floats2half2_rn(e0, e1));
                }
            }
        }
        __syncthreads();

        // O += P V  (4 k16 steps over j)
        #pragma unroll
        for (int st = 0; st < 4; st++) {
            const int kb = st * 8;
            unsigned af[2][4], bf[2][2];
            #pragma unroll
            for (int tm = 0; tm < 2; tm++) {
                const int r = wm*32 + tm*16 + a_r;
                ldsm4(af[tm][0], af[tm][1], af[tm][2], af[tm][3],
                      Ps + r*PJH + kb + a_kh);
            }
            {
                const int n = wn*16 + b_r;
                ldsm4(bf[0][0], bf[0][1], bf[1][0], bf[1][1],
                      Vt + n*PJH + kb + b_kh);
            }
            #pragma unroll
            for (int tm = 0; tm < 2; tm++)
                #pragma unroll
                for (int tn = 0; tn < 2; tn++)
                    mma16(acc[tm][tn][0], acc[tm][tn][1], acc[tm][tn][2], acc[tm][tn][3],
                          af[tm][0], af[tm][1], af[tm][2], af[tm][3],
                          bf[tn][0], bf[tn][1]);
        }
    }

    // row-sum reduce: tig lanes (shfl), then n-warps (smem)
    #pragma unroll
    for (int s2 = 0; s2 < 4; s2++) {
        float r = rsum[s2];
        r += __shfl_xor_sync(0xffffffffu, r, 1);
        r += __shfl_xor_sync(0xffffffffu, r, 2);
        if (tig == 0) {
            const int il = wm*32 + (s2 >> 1)*16 + grp + (s2 & 1)*8;
            red[il*4 + wn] = r;
        }
    }
    __syncthreads();

    #pragma unroll
    for (int tm = 0; tm < 2; tm++) {
        #pragma unroll
        for (int hc = 0; hc < 2; hc++) {
            const int il = wm*32 + tm*16 + grp + hc*8;
            float inv = 1.f / (red[il*4+0] + red[il*4+1] + red[il*4+2] + red[il*4+3]);
            #pragma unroll
            for (int tn = 0; tn < 2; tn++) {
                const int d0 = wn*16 + tn*8 + tig*2;
                float o0 = acc[tm][tn][hc*2+0] * inv;
                float o1 = acc[tm][tn][hc*2+1] * inv;
                *(unsigned*)(Og + base + (size_t)(i0 + il) * Hh + d0) =
                    h2u(__floats2half2_rn(o0, o1));
            }
        }
    }
}

// ---------------- gated = sigmoid(U) * pooled (half in/out) ----------------
__global__ void gate_k(const __half* __restrict__ U, const __half* __restrict__ P,
                       __half* __restrict__ G) {
    int i = blockIdx.x * blockDim.x + threadIdx.x;   // over Mr*Hh/4
    uint2 uu = *(const uint2*)(U + (size_t)i*4);
    uint2 pp = *(const uint2*)(P + (size_t)i*4);
    float2 u0 = __half22float2(*reinterpret_cast<__half2*>(&uu.x));
    float2 u1 = __half22float2(*reinterpret_cast<__half2*>(&uu.y));
    float2 p0 = __half22float2(*reinterpret_cast<__half2*>(&pp.x));
    float2 p1 = __half22float2(*reinterpret_cast<__half2*>(&pp.y));
    uint2 o;
    o.x = h2u(__floats2half2_rn(p0.x / (1.f + expf(-u0.x)), p0.y / (1.f + expf(-u0.y))));
    o.y = h2u(__floats2half2_rn(p1.x / (1.f + expf(-u1.x)), p1.y / (1.f + expf(-u1.y))));
    *(uint2*)(G + (size_t)i*4) = o;
}

// ---------------- launch ----------------
extern "C" void kernel_launch(void* const* d_in, const int* in_sizes, int n_in,
                              void* d_out, int out_size) {
    const float* x    = (const float*)d_in[0];
    // d_in[1] attn_mask: all-True, no-op. d_in[2] pos_ids: unused by reference rope.
    const float* wq   = (const float*)d_in[3];
    const float* wk   = (const float*)d_in[4];
    const float* wv   = (const float*)d_in[5];
    const float* wu   = (const float*)d_in[6];
    const float* wo   = (const float*)d_in[7];
    const float* f1w  = (const float*)d_in[8];
    const float* f1b  = (const float*)d_in[9];
    const float* f2w  = (const float*)d_in[10];
    const float* f2b  = (const float*)d_in[11];
    const float* rmsw = (const float*)d_in[12];
    const float* rtab = (const float*)d_in[13];
    const float* gw   = (const float*)d_in[14];
    const float* rw   = (const float*)d_in[15];
    float* out = (float*)d_out;

    static __half *zh = nullptr, *qh, *kh, *vh, *uh, *ph, *fh, *wh;
    static float *o1, *trig;
    if (!zh) {
        cudaGetSymbolAddress((void**)&zh,   g_zh);
        cudaGetSymbolAddress((void**)&qh,   g_qh);
        cudaGetSymbolAddress((void**)&kh,   g_kh);
        cudaGetSymbolAddress((void**)&vh,   g_vh);
        cudaGetSymbolAddress((void**)&uh,   g_uh);
        cudaGetSymbolAddress((void**)&ph,   g_ph);
        cudaGetSymbolAddress((void**)&fh,   g_fh);
        cudaGetSymbolAddress((void**)&wh,   g_wh);
        cudaGetSymbolAddress((void**)&o1,   g_o1);
        cudaGetSymbolAddress((void**)&trig, g_trig);
    }

    // 1. all weights -> half, one launch
    cvtall_k<<<(int)((13*(size_t)(WSZ/4) + 255)/256), 256>>>(wq, wk, wv, wu, wo, f1w, f2w, wh);

    // 2. RMSNorm -> zh (half)
    rmsnorm_k<<<Mr, 256>>>(x, rmsw, zh);

    // 3. trig table
    sincos_k<<<(Tt*32 + 255)/256, 256>>>(trig);

    // 4. projections -> qh,kh,vh,uh (half)   [ncu capture slot]
    proj4_tc<<<dim3(Hh/128, Mr/128, 4), 128>>>(zh, wh, qh, kh, vh, uh);

    // 5. RoPE on qh,kh
    rope2_k<<<(2*Mr*512)/256, 256>>>(qh, kh, trig);

    // 6. attention -> ph (half)
    attn_tc<<<dim3(Tt/64, Bb*NHh), 256>>>(qh, kh, vh, rtab, ph);

    // 7. gated = sigmoid(uh)*ph -> zh (half; zh free after proj)
    gate_k<<<(Mr*Hh/4)/256, 256>>>(uh, ph, zh);

    // 8. wo GEMM + residual mix -> o1 (float exact) + ph (half copy; ph free now)
    gemm_tc<1><<<dim3(Hh/128, Mr/128), 128>>>(zh, wh + 4*(size_t)WSZ,
        Mr, Hh, Hh, nullptr, o1, nullptr, nullptr, x, gw, rw, ph);

    // 9. FFN1 + bias + gelu -> fh (half)
    gemm_tc<2><<<dim3(FFN/128, Mr/128), 128>>>(ph, wh + 5*(size_t)WSZ,
        Mr, FFN, Hh, fh, nullptr, f1b, nullptr, nullptr, nullptr, nullptr, nullptr);

    // 10. FFN2 + bias + residual(o1) -> out (float)
    gemm_tc<3><<<dim3(Hh/128, Mr/128), 128>>>(fh, wh + 9*(size_t)WSZ,
        Mr, Hh, FFN, nullptr, out, f2b, o1, nullptr, nullptr, nullptr, nullptr);
}